// round 12
// baseline (speedup 1.0000x reference)
#include <cuda_runtime.h>
#include <math.h>

#define C_CH   128
#define SPA    4096
#define BATCH  2
#define HEADS  4
#define DHEAD  32
#define GROUPS 32
#define CPG    4
#define HTOT   128
#define QKV_R  384
#define EPSV   1e-5f

#define NC     8                 // split-K chunks over keys
#define CHUNK  (SPA / NC)        // 512 keys per chunk
#define MT     64                // queries per block
#define KT     32                // keys per inner tile

// Scratch (device globals: allocation-free per harness rules)
__device__ float g_qkv [BATCH * QKV_R * SPA];
__device__ float g_ao  [BATCH * HTOT * SPA];
__device__ float g_mean[BATCH * GROUPS];
__device__ float g_rstd[BATCH * GROUPS];
__device__ float g_pacc[BATCH * HEADS * NC * DHEAD * SPA];
__device__ float g_pm  [BATCH * HEADS * NC * SPA];
__device__ float g_pl  [BATCH * HEADS * NC * SPA];

__device__ __forceinline__ float ex2(float x) {
    float r; asm("ex2.approx.ftz.f32 %0, %1;" : "=f"(r) : "f"(x)); return r;
}
__device__ __forceinline__ unsigned to_tf32(float f) {
    unsigned u; asm("cvt.rna.tf32.f32 %0, %1;" : "=r"(u) : "f"(f)); return u;
}
// D += A(16x8,row) * B(8x8,col) ; tf32 operands, f32 accum
__device__ __forceinline__ void mma_tf32(float* c, const unsigned* a,
                                         unsigned b0, unsigned b1) {
    asm volatile(
        "mma.sync.aligned.m16n8k8.row.col.f32.tf32.tf32.f32 "
        "{%0,%1,%2,%3}, {%4,%5,%6,%7}, {%8,%9}, {%0,%1,%2,%3};"
        : "+f"(c[0]), "+f"(c[1]), "+f"(c[2]), "+f"(c[3])
        : "r"(a[0]), "r"(a[1]), "r"(a[2]), "r"(a[3]), "r"(b0), "r"(b1));
}

// ---------------------------------------------------------------------------
// 1) GroupNorm statistics
// ---------------------------------------------------------------------------
__global__ __launch_bounds__(256) void gn_stats(const float* __restrict__ x) {
    int bg = blockIdx.x;
    const float* p = x + (size_t)bg * (CPG * SPA);
    float s1 = 0.f, s2 = 0.f;
    for (int i = threadIdx.x; i < CPG * SPA; i += 256) {
        float v = p[i];
        s1 += v; s2 += v * v;
    }
    __shared__ float r1[8], r2[8];
    #pragma unroll
    for (int o = 16; o; o >>= 1) {
        s1 += __shfl_down_sync(0xffffffffu, s1, o);
        s2 += __shfl_down_sync(0xffffffffu, s2, o);
    }
    int w = threadIdx.x >> 5, l = threadIdx.x & 31;
    if (l == 0) { r1[w] = s1; r2[w] = s2; }
    __syncthreads();
    if (w == 0) {
        s1 = (l < 8) ? r1[l] : 0.f;
        s2 = (l < 8) ? r2[l] : 0.f;
        #pragma unroll
        for (int o = 4; o; o >>= 1) {
            s1 += __shfl_down_sync(0xffffffffu, s1, o);
            s2 += __shfl_down_sync(0xffffffffu, s2, o);
        }
        if (l == 0) {
            const float invN = 1.0f / (CPG * SPA);
            float mean = s1 * invN;
            float var  = s2 * invN - mean * mean;
            g_mean[bg] = mean;
            g_rstd[bg] = rsqrtf(var + EPSV);
        }
    }
}

// ---------------------------------------------------------------------------
// 2) QKV GEMM with fused GroupNorm on the activation load
// ---------------------------------------------------------------------------
#define BM 64
#define BN 64
#define BK 32

__global__ __launch_bounds__(256) void qkv_gemm(const float* __restrict__ x,
                                                const float* __restrict__ w,
                                                const float* __restrict__ gamma,
                                                const float* __restrict__ beta) {
    int b  = blockIdx.z;
    int m0 = blockIdx.y * BM;
    int n0 = blockIdx.x * BN;
    __shared__ float As[BM * BK];
    __shared__ float Bs[BK * BN];
    int tid = threadIdx.x;
    int tx = tid & 15, ty = tid >> 4;
    float acc[4][4] = {};
    const float* xb = x + (size_t)b * C_CH * SPA;

    for (int k0 = 0; k0 < C_CH; k0 += BK) {
        for (int i = tid; i < BM * BK; i += 256) {
            int row = i / BK, col = i % BK;
            As[i] = w[(size_t)(m0 + row) * C_CH + k0 + col];
        }
        for (int i = tid; i < BK * BN; i += 256) {
            int kk = i / BN, j = i % BN;
            int c = k0 + kk;
            int g = c >> 2;
            float mv = g_mean[b * GROUPS + g];
            float rs = g_rstd[b * GROUPS + g];
            float v = xb[(size_t)c * SPA + n0 + j];
            Bs[i] = (v - mv) * rs * gamma[c] + beta[c];
        }
        __syncthreads();
        #pragma unroll
        for (int kk = 0; kk < BK; kk++) {
            float a[4], bb[4];
            #pragma unroll
            for (int i = 0; i < 4; i++) a[i] = As[(ty * 4 + i) * BK + kk];
            #pragma unroll
            for (int j = 0; j < 4; j++) bb[j] = Bs[kk * BN + tx * 4 + j];
            #pragma unroll
            for (int i = 0; i < 4; i++)
                #pragma unroll
                for (int j = 0; j < 4; j++) acc[i][j] += a[i] * bb[j];
        }
        __syncthreads();
    }
    float* outb = g_qkv + (size_t)b * QKV_R * SPA;
    #pragma unroll
    for (int i = 0; i < 4; i++)
        #pragma unroll
        for (int j = 0; j < 4; j++)
            outb[(size_t)(m0 + ty * 4 + i) * SPA + n0 + tx * 4 + j] = acc[i][j];
}

// ---------------------------------------------------------------------------
// 3a) Flash attention partial — tf32 mma.sync, DOUBLE-BUFFERED K/V pipeline.
//     Per tile: prefetch next K/V into registers during mma; ONE sync/tile.
//     Grid: (64, HEADS*NC=32, 2) = 4096 blocks of 128 threads.
// ---------------------------------------------------------------------------
__global__ __launch_bounds__(128) void attn_partial() {
    int qt = blockIdx.x;
    int yc = blockIdx.y;
    int b  = blockIdx.z;
    int n  = yc >> 3, c = yc & (NC - 1);
    int t  = threadIdx.x;
    int w  = t >> 5, lane = t & 31;
    int g  = lane >> 2, tg = lane & 3;     // mma fragment coords
    int r0 = w * 16 + g;                   // this thread's first q-row (of 2)

    // smem: s_buf = Q stage [32][72] f32, then reused as P tile [64][36] tf32
    __shared__ __align__(16) unsigned s_buf[2304];
    __shared__ __align__(16) unsigned s_kh[2][KT * 36];
    __shared__ __align__(16) unsigned s_kl[2][KT * 36];
    __shared__ __align__(16) unsigned s_v [2][KT * 36];

    const float* qkv_b = g_qkv + (size_t)b * QKV_R * SPA;
    const float* qptr = qkv_b + (size_t)(n * DHEAD) * SPA;
    const float* kptr = qkv_b + (size_t)(HTOT + n * DHEAD) * SPA;
    const float* vptr = qkv_b + (size_t)(2 * HTOT + n * DHEAD) * SPA;
    int s0 = qt * MT;

    const float scale2 = 0.17677669529663687f * 1.4426950408889634f; // /sqrt(32)*log2e

    // ---- stage Q (scaled f32) as [d][72], coalesced + conflict-free ----
    float* sQ = (float*)s_buf;
    for (int idx = t; idx < MT * DHEAD; idx += 128) {
        int d = idx >> 6, row = idx & 63;
        sQ[d * 72 + row] = qptr[(size_t)d * SPA + s0 + row] * scale2;
    }
    __syncthreads();

    // ---- extract Q fragments, split hi/lo tf32 (for 3xTF32 QK) ----
    unsigned qh[4][4], ql[4][4];
    #pragma unroll
    for (int ks = 0; ks < 4; ks++) {
        int d = ks * 8 + tg;
        float v0 = sQ[d * 72 + r0];
        float v1 = sQ[d * 72 + r0 + 8];
        float v2 = sQ[(d + 4) * 72 + r0];
        float v3 = sQ[(d + 4) * 72 + r0 + 8];
        qh[ks][0] = to_tf32(v0); ql[ks][0] = to_tf32(v0 - __uint_as_float(qh[ks][0]));
        qh[ks][1] = to_tf32(v1); ql[ks][1] = to_tf32(v1 - __uint_as_float(qh[ks][1]));
        qh[ks][2] = to_tf32(v2); ql[ks][2] = to_tf32(v2 - __uint_as_float(qh[ks][2]));
        qh[ks][3] = to_tf32(v3); ql[ks][3] = to_tf32(v3 - __uint_as_float(qh[ks][3]));
    }
    __syncthreads();                       // s_buf now becomes P tile
    unsigned* sP = s_buf;                  // [64][36] tf32 bits

    float m0 = -1e30f, m1 = -1e30f, l0 = 0.f, l1 = 0.f;
    float of[4][4] = {};                   // O accum fragments [ntile(d)][4]

    int jbeg = c * CHUNK, jend = jbeg + CHUNK;
    int jrow = t >> 2;                     // fill coords (fixed per thread)

    float kreg[8], vreg[8];
    // ---- prologue: load + store tile 0 into buffer 0 ----
    #pragma unroll
    for (int k = 0; k < 8; k++) {
        int d = (t & 3) + 4 * k;
        kreg[k] = kptr[(size_t)d * SPA + jbeg + jrow];
        vreg[k] = vptr[(size_t)d * SPA + jbeg + jrow];
    }
    #pragma unroll
    for (int k = 0; k < 8; k++) {
        int d = (t & 3) + 4 * k;
        unsigned h = to_tf32(kreg[k]);
        s_kh[0][jrow * 36 + d] = h;
        s_kl[0][jrow * 36 + d] = to_tf32(kreg[k] - __uint_as_float(h));
        s_v [0][jrow * 36 + d] = to_tf32(vreg[k]);
    }
    __syncthreads();

    int cur = 0;
    for (int j0 = jbeg; j0 < jend; j0 += KT) {
        bool has_next = (j0 + KT < jend);
        // ---- prefetch next tile into registers (LDGs overlap mma below) ----
        if (has_next) {
            #pragma unroll
            for (int k = 0; k < 8; k++) {
                int d = (t & 3) + 4 * k;
                kreg[k] = kptr[(size_t)d * SPA + j0 + KT + jrow];
                vreg[k] = vptr[(size_t)d * SPA + j0 + KT + jrow];
            }
        }

        const unsigned* kh = s_kh[cur];
        const unsigned* kl = s_kl[cur];
        const unsigned* vv = s_v [cur];

        // ---- S = Q @ K^T via 3xTF32: QhKh + QhKl + QlKh ----
        float sc[4][4] = {};
        #pragma unroll
        for (int ks = 0; ks < 4; ks++) {
            #pragma unroll
            for (int nt = 0; nt < 4; nt++) {
                int kr = (nt * 8 + g) * 36 + ks * 8 + tg;  // key row, d col
                unsigned bh0 = kh[kr], bh1 = kh[kr + 4];
                unsigned bl0 = kl[kr], bl1 = kl[kr + 4];
                mma_tf32(sc[nt], qh[ks], bh0, bh1);
                mma_tf32(sc[nt], qh[ks], bl0, bl1);
                mma_tf32(sc[nt], ql[ks], bh0, bh1);
            }
        }

        // ---- softmax (log2 domain) on fragments ----
        float rm0 = fmaxf(fmaxf(sc[0][0], sc[0][1]), fmaxf(sc[1][0], sc[1][1]));
        rm0 = fmaxf(rm0, fmaxf(fmaxf(sc[2][0], sc[2][1]), fmaxf(sc[3][0], sc[3][1])));
        float rm1 = fmaxf(fmaxf(sc[0][2], sc[0][3]), fmaxf(sc[1][2], sc[1][3]));
        rm1 = fmaxf(rm1, fmaxf(fmaxf(sc[2][2], sc[2][3]), fmaxf(sc[3][2], sc[3][3])));
        rm0 = fmaxf(rm0, __shfl_xor_sync(0xffffffffu, rm0, 1));
        rm0 = fmaxf(rm0, __shfl_xor_sync(0xffffffffu, rm0, 2));
        rm1 = fmaxf(rm1, __shfl_xor_sync(0xffffffffu, rm1, 1));
        rm1 = fmaxf(rm1, __shfl_xor_sync(0xffffffffu, rm1, 2));
        float nm0 = fmaxf(m0, rm0), nm1 = fmaxf(m1, rm1);
        float c0 = ex2(m0 - nm0), c1 = ex2(m1 - nm1);
        l0 *= c0; l1 *= c1;
        #pragma unroll
        for (int nt = 0; nt < 4; nt++) {
            of[nt][0] *= c0; of[nt][1] *= c0;
            of[nt][2] *= c1; of[nt][3] *= c1;
        }
        m0 = nm0; m1 = nm1;

        float ps0 = 0.f, ps1 = 0.f;
        #pragma unroll
        for (int nt = 0; nt < 4; nt++) {
            float p00 = ex2(sc[nt][0] - m0);
            float p01 = ex2(sc[nt][1] - m0);
            float p10 = ex2(sc[nt][2] - m1);
            float p11 = ex2(sc[nt][3] - m1);
            ps0 += p00 + p01; ps1 += p10 + p11;
            int col = nt * 8 + 2 * tg;
            sP[r0 * 36 + col]           = to_tf32(p00);
            sP[r0 * 36 + col + 1]       = to_tf32(p01);
            sP[(r0 + 8) * 36 + col]     = to_tf32(p10);
            sP[(r0 + 8) * 36 + col + 1] = to_tf32(p11);
        }
        l0 += ps0; l1 += ps1;
        __syncwarp();                      // warp reads only its own P rows

        // ---- O += P @ V (single tf32) ----
        #pragma unroll
        for (int ks = 0; ks < 4; ks++) {
            unsigned af[4];
            af[0] = sP[r0 * 36 + ks * 8 + tg];
            af[1] = sP[(r0 + 8) * 36 + ks * 8 + tg];
            af[2] = sP[r0 * 36 + ks * 8 + tg + 4];
            af[3] = sP[(r0 + 8) * 36 + ks * 8 + tg + 4];
            #pragma unroll
            for (int nt = 0; nt < 4; nt++) {
                unsigned b0 = vv[(ks * 8 + tg) * 36 + nt * 8 + g];
                unsigned b1 = vv[(ks * 8 + tg + 4) * 36 + nt * 8 + g];
                mma_tf32(of[nt], af, b0, b1);
            }
        }

        // ---- store staged tile into the other buffer; ONE sync/tile ----
        if (has_next) {
            int nb = cur ^ 1;
            #pragma unroll
            for (int k = 0; k < 8; k++) {
                int d = (t & 3) + 4 * k;
                unsigned h = to_tf32(kreg[k]);
                s_kh[nb][jrow * 36 + d] = h;
                s_kl[nb][jrow * 36 + d] = to_tf32(kreg[k] - __uint_as_float(h));
                s_v [nb][jrow * 36 + d] = to_tf32(vreg[k]);
            }
            __syncthreads();
            cur = nb;
        }
    }

    // ---- finalize l (quad reduce) and write partials ----
    l0 += __shfl_xor_sync(0xffffffffu, l0, 1);
    l0 += __shfl_xor_sync(0xffffffffu, l0, 2);
    l1 += __shfl_xor_sync(0xffffffffu, l1, 1);
    l1 += __shfl_xor_sync(0xffffffffu, l1, 2);

    size_t base = (size_t)(b * HEADS + n) * NC + c;
    if (tg == 0) {
        g_pm[base * SPA + s0 + r0]     = m0;
        g_pl[base * SPA + s0 + r0]     = l0;
        g_pm[base * SPA + s0 + r0 + 8] = m1;
        g_pl[base * SPA + s0 + r0 + 8] = l1;
    }
    float* pa = g_pacc + base * (DHEAD * SPA);
    #pragma unroll
    for (int nt = 0; nt < 4; nt++) {
        int d0 = nt * 8 + 2 * tg;
        pa[(size_t)d0 * SPA + s0 + r0]           = of[nt][0];
        pa[(size_t)(d0 + 1) * SPA + s0 + r0]     = of[nt][1];
        pa[(size_t)d0 * SPA + s0 + r0 + 8]       = of[nt][2];
        pa[(size_t)(d0 + 1) * SPA + s0 + r0 + 8] = of[nt][3];
    }
}

// ---------------------------------------------------------------------------
// 3b) Combine split-K partials -> g_ao (m/l log2-domain)
// ---------------------------------------------------------------------------
__global__ __launch_bounds__(256) void attn_combine() {
    int t = threadIdx.x;
    int s = blockIdx.x * 256 + t;
    int yb = blockIdx.y;
    int n = yb >> 2, dbase = (yb & 3) * 8;
    int b = blockIdx.z;
    size_t base = (size_t)(b * HEADS + n) * NC;

    float pm[NC];
    float m = -1e30f;
    #pragma unroll
    for (int c = 0; c < NC; c++) {
        pm[c] = g_pm[(base + c) * SPA + s];
        m = fmaxf(m, pm[c]);
    }
    float wgt[NC];
    float L = 0.f;
    #pragma unroll
    for (int c = 0; c < NC; c++) {
        wgt[c] = ex2(fmaxf(pm[c] - m, -120.0f));
        L += g_pl[(base + c) * SPA + s] * wgt[c];
    }
    float invL = 1.0f / L;
    #pragma unroll
    for (int c = 0; c < NC; c++) wgt[c] *= invL;

    float* ao = g_ao + ((size_t)b * HTOT + n * DHEAD) * SPA;
    #pragma unroll
    for (int dd = 0; dd < 8; dd++) {
        int d = dbase + dd;
        float a = 0.f;
        #pragma unroll
        for (int c = 0; c < NC; c++)
            a += g_pacc[((base + c) * DHEAD + d) * SPA + s] * wgt[c];
        ao[(size_t)d * SPA + s] = a;
    }
}

// ---------------------------------------------------------------------------
// 4) Output projection
// ---------------------------------------------------------------------------
__global__ __launch_bounds__(256) void out_gemm(const float* __restrict__ w,
                                                const float* __restrict__ bias,
                                                float* __restrict__ y) {
    int b  = blockIdx.z;
    int m0 = blockIdx.y * BM;
    int n0 = blockIdx.x * BN;
    __shared__ float As[BM * BK];
    __shared__ float Bs[BK * BN];
    int tid = threadIdx.x;
    int tx = tid & 15, ty = tid >> 4;
    float acc[4][4] = {};
    const float* ab = g_ao + (size_t)b * HTOT * SPA;

    for (int k0 = 0; k0 < HTOT; k0 += BK) {
        for (int i = tid; i < BM * BK; i += 256) {
            int row = i / BK, col = i % BK;
            As[i] = w[(size_t)(m0 + row) * HTOT + k0 + col];
        }
        for (int i = tid; i < BK * BN; i += 256) {
            int kk = i / BN, j = i % BN;
            Bs[i] = ab[(size_t)(k0 + kk) * SPA + n0 + j];
        }
        __syncthreads();
        #pragma unroll
        for (int kk = 0; kk < BK; kk++) {
            float a[4], bb[4];
            #pragma unroll
            for (int i = 0; i < 4; i++) a[i] = As[(ty * 4 + i) * BK + kk];
            #pragma unroll
            for (int j = 0; j < 4; j++) bb[j] = Bs[kk * BN + tx * 4 + j];
            #pragma unroll
            for (int i = 0; i < 4; i++)
                #pragma unroll
                for (int j = 0; j < 4; j++) acc[i][j] += a[i] * bb[j];
        }
        __syncthreads();
    }
    #pragma unroll
    for (int i = 0; i < 4; i++) {
        float bv = bias[m0 + ty * 4 + i];
        #pragma unroll
        for (int j = 0; j < 4; j++)
            y[(size_t)(b * C_CH + m0 + ty * 4 + i) * SPA + n0 + tx * 4 + j] =
                acc[i][j] + bv;
    }
}

// ---------------------------------------------------------------------------
extern "C" void kernel_launch(void* const* d_in, const int* in_sizes, int n_in,
                              void* d_out, int out_size) {
    const float* x     = (const float*)d_in[0];
    const float* gamma = (const float*)d_in[1];
    const float* beta  = (const float*)d_in[2];
    const float* w_qkv = (const float*)d_in[3];
    const float* w_out = (const float*)d_in[4];
    const float* b_out = (const float*)d_in[5];
    float* y = (float*)d_out;

    gn_stats<<<BATCH * GROUPS, 256>>>(x);
    qkv_gemm<<<dim3(SPA / BN, QKV_R / BM, BATCH), 256>>>(x, w_qkv, gamma, beta);
    attn_partial<<<dim3(SPA / MT, HEADS * NC, BATCH), 128>>>();
    attn_combine<<<dim3(SPA / 256, HEADS * 4, BATCH), 256>>>();
    out_gemm<<<dim3(SPA / BN, C_CH / BM, BATCH), 256>>>(w_out, b_out, y);
}

// round 13
// speedup vs baseline: 1.0574x; 1.0574x over previous
#include <cuda_runtime.h>
#include <math.h>

#define C_CH   128
#define SPA    4096
#define BATCH  2
#define HEADS  4
#define DHEAD  32
#define GROUPS 32
#define CPG    4
#define HTOT   128
#define QKV_R  384
#define EPSV   1e-5f

#define NC     8                 // split-K chunks over keys
#define CHUNK  (SPA / NC)        // 512 keys per chunk
#define MT     64                // queries per block
#define KT     32                // keys per inner tile

// Scratch (device globals: allocation-free per harness rules)
__device__ float g_qkv [BATCH * QKV_R * SPA];
__device__ float g_ao  [BATCH * HTOT * SPA];
__device__ float g_mean[BATCH * GROUPS];
__device__ float g_rstd[BATCH * GROUPS];
__device__ float g_pacc[BATCH * HEADS * NC * DHEAD * SPA];
__device__ float g_pm  [BATCH * HEADS * NC * SPA];
__device__ float g_pl  [BATCH * HEADS * NC * SPA];

__device__ __forceinline__ float ex2(float x) {
    float r; asm("ex2.approx.ftz.f32 %0, %1;" : "=f"(r) : "f"(x)); return r;
}
__device__ __forceinline__ unsigned to_tf32(float f) {
    unsigned u; asm("cvt.rna.tf32.f32 %0, %1;" : "=r"(u) : "f"(f)); return u;
}
// D += A(16x8,row) * B(8x8,col) ; tf32 operands, f32 accum
__device__ __forceinline__ void mma_tf32(float* c, const unsigned* a,
                                         unsigned b0, unsigned b1) {
    asm volatile(
        "mma.sync.aligned.m16n8k8.row.col.f32.tf32.tf32.f32 "
        "{%0,%1,%2,%3}, {%4,%5,%6,%7}, {%8,%9}, {%0,%1,%2,%3};"
        : "+f"(c[0]), "+f"(c[1]), "+f"(c[2]), "+f"(c[3])
        : "r"(a[0]), "r"(a[1]), "r"(a[2]), "r"(a[3]), "r"(b0), "r"(b1));
}

// ---------------------------------------------------------------------------
// 1) GroupNorm statistics
// ---------------------------------------------------------------------------
__global__ __launch_bounds__(256) void gn_stats(const float* __restrict__ x) {
    int bg = blockIdx.x;
    const float* p = x + (size_t)bg * (CPG * SPA);
    float s1 = 0.f, s2 = 0.f;
    for (int i = threadIdx.x; i < CPG * SPA; i += 256) {
        float v = p[i];
        s1 += v; s2 += v * v;
    }
    __shared__ float r1[8], r2[8];
    #pragma unroll
    for (int o = 16; o; o >>= 1) {
        s1 += __shfl_down_sync(0xffffffffu, s1, o);
        s2 += __shfl_down_sync(0xffffffffu, s2, o);
    }
    int w = threadIdx.x >> 5, l = threadIdx.x & 31;
    if (l == 0) { r1[w] = s1; r2[w] = s2; }
    __syncthreads();
    if (w == 0) {
        s1 = (l < 8) ? r1[l] : 0.f;
        s2 = (l < 8) ? r2[l] : 0.f;
        #pragma unroll
        for (int o = 4; o; o >>= 1) {
            s1 += __shfl_down_sync(0xffffffffu, s1, o);
            s2 += __shfl_down_sync(0xffffffffu, s2, o);
        }
        if (l == 0) {
            const float invN = 1.0f / (CPG * SPA);
            float mean = s1 * invN;
            float var  = s2 * invN - mean * mean;
            g_mean[bg] = mean;
            g_rstd[bg] = rsqrtf(var + EPSV);
        }
    }
}

// ---------------------------------------------------------------------------
// 2) QKV GEMM with fused GroupNorm on the activation load
// ---------------------------------------------------------------------------
#define BM 64
#define BN 64
#define BK 32

__global__ __launch_bounds__(256) void qkv_gemm(const float* __restrict__ x,
                                                const float* __restrict__ w,
                                                const float* __restrict__ gamma,
                                                const float* __restrict__ beta) {
    int b  = blockIdx.z;
    int m0 = blockIdx.y * BM;
    int n0 = blockIdx.x * BN;
    __shared__ float As[BM * BK];
    __shared__ float Bs[BK * BN];
    int tid = threadIdx.x;
    int tx = tid & 15, ty = tid >> 4;
    float acc[4][4] = {};
    const float* xb = x + (size_t)b * C_CH * SPA;

    for (int k0 = 0; k0 < C_CH; k0 += BK) {
        for (int i = tid; i < BM * BK; i += 256) {
            int row = i / BK, col = i % BK;
            As[i] = w[(size_t)(m0 + row) * C_CH + k0 + col];
        }
        for (int i = tid; i < BK * BN; i += 256) {
            int kk = i / BN, j = i % BN;
            int c = k0 + kk;
            int g = c >> 2;
            float mv = g_mean[b * GROUPS + g];
            float rs = g_rstd[b * GROUPS + g];
            float v = xb[(size_t)c * SPA + n0 + j];
            Bs[i] = (v - mv) * rs * gamma[c] + beta[c];
        }
        __syncthreads();
        #pragma unroll
        for (int kk = 0; kk < BK; kk++) {
            float a[4], bb[4];
            #pragma unroll
            for (int i = 0; i < 4; i++) a[i] = As[(ty * 4 + i) * BK + kk];
            #pragma unroll
            for (int j = 0; j < 4; j++) bb[j] = Bs[kk * BN + tx * 4 + j];
            #pragma unroll
            for (int i = 0; i < 4; i++)
                #pragma unroll
                for (int j = 0; j < 4; j++) acc[i][j] += a[i] * bb[j];
        }
        __syncthreads();
    }
    float* outb = g_qkv + (size_t)b * QKV_R * SPA;
    #pragma unroll
    for (int i = 0; i < 4; i++)
        #pragma unroll
        for (int j = 0; j < 4; j++)
            outb[(size_t)(m0 + ty * 4 + i) * SPA + n0 + tx * 4 + j] = acc[i][j];
}

// ---------------------------------------------------------------------------
// 3a) Flash attention partial — tf32 mma.sync, 2xTF32 QK (QhKh + QhKl).
//     Single-buffer loop (R11 structure; double-buffer proved neutral).
//     Grid: (64, HEADS*NC=32, 2) = 4096 blocks of 128 threads.
// ---------------------------------------------------------------------------
__global__ __launch_bounds__(128) void attn_partial() {
    int qt = blockIdx.x;
    int yc = blockIdx.y;
    int b  = blockIdx.z;
    int n  = yc >> 3, c = yc & (NC - 1);
    int t  = threadIdx.x;
    int w  = t >> 5, lane = t & 31;
    int g  = lane >> 2, tg = lane & 3;     // mma fragment coords
    int r0 = w * 16 + g;                   // this thread's first q-row (of 2)

    // smem: s_buf = Q stage [32][72] f32, then reused as P tile [64][36] tf32
    __shared__ __align__(16) unsigned s_buf[2304];
    __shared__ __align__(16) unsigned s_kh[KT * 36];
    __shared__ __align__(16) unsigned s_kl[KT * 36];
    __shared__ __align__(16) unsigned s_v [KT * 36];

    const float* qkv_b = g_qkv + (size_t)b * QKV_R * SPA;
    const float* qptr = qkv_b + (size_t)(n * DHEAD) * SPA;
    const float* kptr = qkv_b + (size_t)(HTOT + n * DHEAD) * SPA;
    const float* vptr = qkv_b + (size_t)(2 * HTOT + n * DHEAD) * SPA;
    int s0 = qt * MT;

    const float scale2 = 0.17677669529663687f * 1.4426950408889634f; // /sqrt(32)*log2e

    // ---- stage Q (scaled f32) as [d][72], coalesced + conflict-free ----
    float* sQ = (float*)s_buf;
    for (int idx = t; idx < MT * DHEAD; idx += 128) {
        int d = idx >> 6, row = idx & 63;
        sQ[d * 72 + row] = qptr[(size_t)d * SPA + s0 + row] * scale2;
    }
    __syncthreads();

    // ---- extract Q fragments (hi only needed for mma; hi split on K side) --
    unsigned qh[4][4];
    #pragma unroll
    for (int ks = 0; ks < 4; ks++) {
        int d = ks * 8 + tg;
        qh[ks][0] = to_tf32(sQ[d * 72 + r0]);
        qh[ks][1] = to_tf32(sQ[d * 72 + r0 + 8]);
        qh[ks][2] = to_tf32(sQ[(d + 4) * 72 + r0]);
        qh[ks][3] = to_tf32(sQ[(d + 4) * 72 + r0 + 8]);
    }
    // NOTE: Q is quantized once (hi only); K carries hi+lo. Dropped terms:
    // Ql*Kh and Ql*Kl ~ 2^-11 relative -> ~1e-4..3e-4 output rel err.
    __syncthreads();                       // s_buf now becomes P tile
    unsigned* sP = s_buf;                  // [64][36] tf32 bits

    float m0 = -1e30f, m1 = -1e30f, l0 = 0.f, l1 = 0.f;
    float of[4][4] = {};                   // O accum fragments [ntile(d)][4]

    int jbeg = c * CHUNK, jend = jbeg + CHUNK;
    for (int j0 = jbeg; j0 < jend; j0 += KT) {
        __syncthreads();
        // ---- fill K (hi/lo tf32) and V (tf32), conflict-free STS ----
        #pragma unroll
        for (int k = 0; k < 8; k++) {
            int j = t >> 2, d = (t & 3) + 4 * k;
            float kv = kptr[(size_t)d * SPA + j0 + j];
            unsigned h = to_tf32(kv);
            s_kh[j * 36 + d] = h;
            s_kl[j * 36 + d] = to_tf32(kv - __uint_as_float(h));
            s_v [j * 36 + d] = to_tf32(vptr[(size_t)d * SPA + j0 + j]);
        }
        __syncthreads();

        // ---- S = Q @ K^T via 2xTF32: Qh*Kh + Qh*Kl ----
        float sc[4][4] = {};
        #pragma unroll
        for (int ks = 0; ks < 4; ks++) {
            #pragma unroll
            for (int nt = 0; nt < 4; nt++) {
                int kr = (nt * 8 + g) * 36 + ks * 8 + tg;  // key row, d col
                mma_tf32(sc[nt], qh[ks], s_kh[kr], s_kh[kr + 4]);
                mma_tf32(sc[nt], qh[ks], s_kl[kr], s_kl[kr + 4]);
            }
        }

        // ---- softmax (log2 domain) on fragments ----
        float rm0 = fmaxf(fmaxf(sc[0][0], sc[0][1]), fmaxf(sc[1][0], sc[1][1]));
        rm0 = fmaxf(rm0, fmaxf(fmaxf(sc[2][0], sc[2][1]), fmaxf(sc[3][0], sc[3][1])));
        float rm1 = fmaxf(fmaxf(sc[0][2], sc[0][3]), fmaxf(sc[1][2], sc[1][3]));
        rm1 = fmaxf(rm1, fmaxf(fmaxf(sc[2][2], sc[2][3]), fmaxf(sc[3][2], sc[3][3])));
        rm0 = fmaxf(rm0, __shfl_xor_sync(0xffffffffu, rm0, 1));
        rm0 = fmaxf(rm0, __shfl_xor_sync(0xffffffffu, rm0, 2));
        rm1 = fmaxf(rm1, __shfl_xor_sync(0xffffffffu, rm1, 1));
        rm1 = fmaxf(rm1, __shfl_xor_sync(0xffffffffu, rm1, 2));
        float nm0 = fmaxf(m0, rm0), nm1 = fmaxf(m1, rm1);
        float c0 = ex2(m0 - nm0), c1 = ex2(m1 - nm1);
        l0 *= c0; l1 *= c1;
        #pragma unroll
        for (int nt = 0; nt < 4; nt++) {
            of[nt][0] *= c0; of[nt][1] *= c0;
            of[nt][2] *= c1; of[nt][3] *= c1;
        }
        m0 = nm0; m1 = nm1;

        float ps0 = 0.f, ps1 = 0.f;
        #pragma unroll
        for (int nt = 0; nt < 4; nt++) {
            float p00 = ex2(sc[nt][0] - m0);
            float p01 = ex2(sc[nt][1] - m0);
            float p10 = ex2(sc[nt][2] - m1);
            float p11 = ex2(sc[nt][3] - m1);
            ps0 += p00 + p01; ps1 += p10 + p11;
            int col = nt * 8 + 2 * tg;
            sP[r0 * 36 + col]           = to_tf32(p00);
            sP[r0 * 36 + col + 1]       = to_tf32(p01);
            sP[(r0 + 8) * 36 + col]     = to_tf32(p10);
            sP[(r0 + 8) * 36 + col + 1] = to_tf32(p11);
        }
        l0 += ps0; l1 += ps1;
        __syncwarp();                      // warp reads only its own P rows

        // ---- O += P @ V (single tf32) ----
        #pragma unroll
        for (int ks = 0; ks < 4; ks++) {
            unsigned af[4];
            af[0] = sP[r0 * 36 + ks * 8 + tg];
            af[1] = sP[(r0 + 8) * 36 + ks * 8 + tg];
            af[2] = sP[r0 * 36 + ks * 8 + tg + 4];
            af[3] = sP[(r0 + 8) * 36 + ks * 8 + tg + 4];
            #pragma unroll
            for (int nt = 0; nt < 4; nt++) {
                unsigned b0 = s_v[(ks * 8 + tg) * 36 + nt * 8 + g];
                unsigned b1 = s_v[(ks * 8 + tg + 4) * 36 + nt * 8 + g];
                mma_tf32(of[nt], af, b0, b1);
            }
        }
    }

    // ---- finalize l (quad reduce) and write partials ----
    l0 += __shfl_xor_sync(0xffffffffu, l0, 1);
    l0 += __shfl_xor_sync(0xffffffffu, l0, 2);
    l1 += __shfl_xor_sync(0xffffffffu, l1, 1);
    l1 += __shfl_xor_sync(0xffffffffu, l1, 2);

    size_t base = (size_t)(b * HEADS + n) * NC + c;
    if (tg == 0) {
        g_pm[base * SPA + s0 + r0]     = m0;
        g_pl[base * SPA + s0 + r0]     = l0;
        g_pm[base * SPA + s0 + r0 + 8] = m1;
        g_pl[base * SPA + s0 + r0 + 8] = l1;
    }
    float* pa = g_pacc + base * (DHEAD * SPA);
    #pragma unroll
    for (int nt = 0; nt < 4; nt++) {
        int d0 = nt * 8 + 2 * tg;
        pa[(size_t)d0 * SPA + s0 + r0]           = of[nt][0];
        pa[(size_t)(d0 + 1) * SPA + s0 + r0]     = of[nt][1];
        pa[(size_t)d0 * SPA + s0 + r0 + 8]       = of[nt][2];
        pa[(size_t)(d0 + 1) * SPA + s0 + r0 + 8] = of[nt][3];
    }
}

// ---------------------------------------------------------------------------
// 3b) Combine split-K partials -> g_ao (m/l log2-domain)
// ---------------------------------------------------------------------------
__global__ __launch_bounds__(256) void attn_combine() {
    int t = threadIdx.x;
    int s = blockIdx.x * 256 + t;
    int yb = blockIdx.y;
    int n = yb >> 2, dbase = (yb & 3) * 8;
    int b = blockIdx.z;
    size_t base = (size_t)(b * HEADS + n) * NC;

    float pm[NC];
    float m = -1e30f;
    #pragma unroll
    for (int c = 0; c < NC; c++) {
        pm[c] = g_pm[(base + c) * SPA + s];
        m = fmaxf(m, pm[c]);
    }
    float wgt[NC];
    float L = 0.f;
    #pragma unroll
    for (int c = 0; c < NC; c++) {
        wgt[c] = ex2(fmaxf(pm[c] - m, -120.0f));
        L += g_pl[(base + c) * SPA + s] * wgt[c];
    }
    float invL = 1.0f / L;
    #pragma unroll
    for (int c = 0; c < NC; c++) wgt[c] *= invL;

    float* ao = g_ao + ((size_t)b * HTOT + n * DHEAD) * SPA;
    #pragma unroll
    for (int dd = 0; dd < 8; dd++) {
        int d = dbase + dd;
        float a = 0.f;
        #pragma unroll
        for (int c = 0; c < NC; c++)
            a += g_pacc[((base + c) * DHEAD + d) * SPA + s] * wgt[c];
        ao[(size_t)d * SPA + s] = a;
    }
}

// ---------------------------------------------------------------------------
// 4) Output projection
// ---------------------------------------------------------------------------
__global__ __launch_bounds__(256) void out_gemm(const float* __restrict__ w,
                                                const float* __restrict__ bias,
                                                float* __restrict__ y) {
    int b  = blockIdx.z;
    int m0 = blockIdx.y * BM;
    int n0 = blockIdx.x * BN;
    __shared__ float As[BM * BK];
    __shared__ float Bs[BK * BN];
    int tid = threadIdx.x;
    int tx = tid & 15, ty = tid >> 4;
    float acc[4][4] = {};
    const float* ab = g_ao + (size_t)b * HTOT * SPA;

    for (int k0 = 0; k0 < HTOT; k0 += BK) {
        for (int i = tid; i < BM * BK; i += 256) {
            int row = i / BK, col = i % BK;
            As[i] = w[(size_t)(m0 + row) * HTOT + k0 + col];
        }
        for (int i = tid; i < BK * BN; i += 256) {
            int kk = i / BN, j = i % BN;
            Bs[i] = ab[(size_t)(k0 + kk) * SPA + n0 + j];
        }
        __syncthreads();
        #pragma unroll
        for (int kk = 0; kk < BK; kk++) {
            float a[4], bb[4];
            #pragma unroll
            for (int i = 0; i < 4; i++) a[i] = As[(ty * 4 + i) * BK + kk];
            #pragma unroll
            for (int j = 0; j < 4; j++) bb[j] = Bs[kk * BN + tx * 4 + j];
            #pragma unroll
            for (int i = 0; i < 4; i++)
                #pragma unroll
                for (int j = 0; j < 4; j++) acc[i][j] += a[i] * bb[j];
        }
        __syncthreads();
    }
    #pragma unroll
    for (int i = 0; i < 4; i++) {
        float bv = bias[m0 + ty * 4 + i];
        #pragma unroll
        for (int j = 0; j < 4; j++)
            y[(size_t)(b * C_CH + m0 + ty * 4 + i) * SPA + n0 + tx * 4 + j] =
                acc[i][j] + bv;
    }
}

// ---------------------------------------------------------------------------
extern "C" void kernel_launch(void* const* d_in, const int* in_sizes, int n_in,
                              void* d_out, int out_size) {
    const float* x     = (const float*)d_in[0];
    const float* gamma = (const float*)d_in[1];
    const float* beta  = (const float*)d_in[2];
    const float* w_qkv = (const float*)d_in[3];
    const float* w_out = (const float*)d_in[4];
    const float* b_out = (const float*)d_in[5];
    float* y = (float*)d_out;

    gn_stats<<<BATCH * GROUPS, 256>>>(x);
    qkv_gemm<<<dim3(SPA / BN, QKV_R / BM, BATCH), 256>>>(x, w_qkv, gamma, beta);
    attn_partial<<<dim3(SPA / MT, HEADS * NC, BATCH), 128>>>();
    attn_combine<<<dim3(SPA / 256, HEADS * 4, BATCH), 256>>>();
    out_gemm<<<dim3(SPA / BN, C_CH / BM, BATCH), 256>>>(w_out, b_out, y);
}

// round 14
// speedup vs baseline: 1.0880x; 1.0289x over previous
#include <cuda_runtime.h>
#include <math.h>

#define C_CH   128
#define SPA    4096
#define BATCH  2
#define HEADS  4
#define DHEAD  32
#define GROUPS 32
#define CPG    4
#define HTOT   128
#define QKV_R  384
#define EPSV   1e-5f

#define NC     4                 // split-K chunks over keys
#define CHUNK  (SPA / NC)        // 1024 keys per chunk
#define MT     64                // queries per block
#define KT     64                // keys staged per fill (2 x 32 compute halves)

// Scratch (device globals: allocation-free per harness rules)
__device__ float g_qkv [BATCH * QKV_R * SPA];
__device__ float g_ao  [BATCH * HTOT * SPA];
__device__ float g_mean[BATCH * GROUPS];
__device__ float g_rstd[BATCH * GROUPS];
__device__ float g_pacc[BATCH * HEADS * NC * DHEAD * SPA];
__device__ float g_pm  [BATCH * HEADS * NC * SPA];
__device__ float g_pl  [BATCH * HEADS * NC * SPA];

__device__ __forceinline__ float ex2(float x) {
    float r; asm("ex2.approx.ftz.f32 %0, %1;" : "=f"(r) : "f"(x)); return r;
}
__device__ __forceinline__ unsigned to_tf32(float f) {
    unsigned u; asm("cvt.rna.tf32.f32 %0, %1;" : "=r"(u) : "f"(f)); return u;
}
// D += A(16x8,row) * B(8x8,col) ; tf32 operands, f32 accum
__device__ __forceinline__ void mma_tf32(float* c, const unsigned* a,
                                         unsigned b0, unsigned b1) {
    asm volatile(
        "mma.sync.aligned.m16n8k8.row.col.f32.tf32.tf32.f32 "
        "{%0,%1,%2,%3}, {%4,%5,%6,%7}, {%8,%9}, {%0,%1,%2,%3};"
        : "+f"(c[0]), "+f"(c[1]), "+f"(c[2]), "+f"(c[3])
        : "r"(a[0]), "r"(a[1]), "r"(a[2]), "r"(a[3]), "r"(b0), "r"(b1));
}

// ---------------------------------------------------------------------------
// 1) GroupNorm statistics
// ---------------------------------------------------------------------------
__global__ __launch_bounds__(256) void gn_stats(const float* __restrict__ x) {
    int bg = blockIdx.x;
    const float* p = x + (size_t)bg * (CPG * SPA);
    float s1 = 0.f, s2 = 0.f;
    for (int i = threadIdx.x; i < CPG * SPA; i += 256) {
        float v = p[i];
        s1 += v; s2 += v * v;
    }
    __shared__ float r1[8], r2[8];
    #pragma unroll
    for (int o = 16; o; o >>= 1) {
        s1 += __shfl_down_sync(0xffffffffu, s1, o);
        s2 += __shfl_down_sync(0xffffffffu, s2, o);
    }
    int w = threadIdx.x >> 5, l = threadIdx.x & 31;
    if (l == 0) { r1[w] = s1; r2[w] = s2; }
    __syncthreads();
    if (w == 0) {
        s1 = (l < 8) ? r1[l] : 0.f;
        s2 = (l < 8) ? r2[l] : 0.f;
        #pragma unroll
        for (int o = 4; o; o >>= 1) {
            s1 += __shfl_down_sync(0xffffffffu, s1, o);
            s2 += __shfl_down_sync(0xffffffffu, s2, o);
        }
        if (l == 0) {
            const float invN = 1.0f / (CPG * SPA);
            float mean = s1 * invN;
            float var  = s2 * invN - mean * mean;
            g_mean[bg] = mean;
            g_rstd[bg] = rsqrtf(var + EPSV);
        }
    }
}

// ---------------------------------------------------------------------------
// 2) QKV GEMM with fused GroupNorm on the activation load
// ---------------------------------------------------------------------------
#define BM 64
#define BN 64
#define BK 32

__global__ __launch_bounds__(256) void qkv_gemm(const float* __restrict__ x,
                                                const float* __restrict__ w,
                                                const float* __restrict__ gamma,
                                                const float* __restrict__ beta) {
    int b  = blockIdx.z;
    int m0 = blockIdx.y * BM;
    int n0 = blockIdx.x * BN;
    __shared__ float As[BM * BK];
    __shared__ float Bs[BK * BN];
    int tid = threadIdx.x;
    int tx = tid & 15, ty = tid >> 4;
    float acc[4][4] = {};
    const float* xb = x + (size_t)b * C_CH * SPA;

    for (int k0 = 0; k0 < C_CH; k0 += BK) {
        for (int i = tid; i < BM * BK; i += 256) {
            int row = i / BK, col = i % BK;
            As[i] = w[(size_t)(m0 + row) * C_CH + k0 + col];
        }
        for (int i = tid; i < BK * BN; i += 256) {
            int kk = i / BN, j = i % BN;
            int c = k0 + kk;
            int g = c >> 2;
            float mv = g_mean[b * GROUPS + g];
            float rs = g_rstd[b * GROUPS + g];
            float v = xb[(size_t)c * SPA + n0 + j];
            Bs[i] = (v - mv) * rs * gamma[c] + beta[c];
        }
        __syncthreads();
        #pragma unroll
        for (int kk = 0; kk < BK; kk++) {
            float a[4], bb[4];
            #pragma unroll
            for (int i = 0; i < 4; i++) a[i] = As[(ty * 4 + i) * BK + kk];
            #pragma unroll
            for (int j = 0; j < 4; j++) bb[j] = Bs[kk * BN + tx * 4 + j];
            #pragma unroll
            for (int i = 0; i < 4; i++)
                #pragma unroll
                for (int j = 0; j < 4; j++) acc[i][j] += a[i] * bb[j];
        }
        __syncthreads();
    }
    float* outb = g_qkv + (size_t)b * QKV_R * SPA;
    #pragma unroll
    for (int i = 0; i < 4; i++)
        #pragma unroll
        for (int j = 0; j < 4; j++)
            outb[(size_t)(m0 + ty * 4 + i) * SPA + n0 + tx * 4 + j] = acc[i][j];
}

// ---------------------------------------------------------------------------
// 3a) Flash attention partial — tf32 mma.sync, 2xTF32 QK.
//     KT=64 keys staged per fill (2 syncs / 64 keys), computed as 2x32 halves.
//     Grid: (64, HEADS*NC=16, 2) = 2048 blocks of 128 threads.
// ---------------------------------------------------------------------------
__global__ __launch_bounds__(128) void attn_partial() {
    int qt = blockIdx.x;
    int yc = blockIdx.y;
    int b  = blockIdx.z;
    int n  = yc >> 2, c = yc & (NC - 1);
    int t  = threadIdx.x;
    int w  = t >> 5, lane = t & 31;
    int g  = lane >> 2, tg = lane & 3;     // mma fragment coords
    int r0 = w * 16 + g;                   // this thread's first q-row (of 2)

    // smem: s_buf = Q stage [32][72] f32, then reused as P tile [64][36] tf32
    __shared__ __align__(16) unsigned s_buf[2304];
    __shared__ __align__(16) unsigned s_kh[KT * 36];
    __shared__ __align__(16) unsigned s_kl[KT * 36];
    __shared__ __align__(16) unsigned s_v [KT * 36];

    const float* qkv_b = g_qkv + (size_t)b * QKV_R * SPA;
    const float* qptr = qkv_b + (size_t)(n * DHEAD) * SPA;
    const float* kptr = qkv_b + (size_t)(HTOT + n * DHEAD) * SPA;
    const float* vptr = qkv_b + (size_t)(2 * HTOT + n * DHEAD) * SPA;
    int s0 = qt * MT;

    const float scale2 = 0.17677669529663687f * 1.4426950408889634f; // /sqrt(32)*log2e

    // ---- stage Q (scaled f32) as [d][72], coalesced + conflict-free ----
    float* sQ = (float*)s_buf;
    for (int idx = t; idx < MT * DHEAD; idx += 128) {
        int d = idx >> 6, row = idx & 63;
        sQ[d * 72 + row] = qptr[(size_t)d * SPA + s0 + row] * scale2;
    }
    __syncthreads();

    // ---- extract Q fragments (hi only; lo carried on K side) ----
    unsigned qh[4][4];
    #pragma unroll
    for (int ks = 0; ks < 4; ks++) {
        int d = ks * 8 + tg;
        qh[ks][0] = to_tf32(sQ[d * 72 + r0]);
        qh[ks][1] = to_tf32(sQ[d * 72 + r0 + 8]);
        qh[ks][2] = to_tf32(sQ[(d + 4) * 72 + r0]);
        qh[ks][3] = to_tf32(sQ[(d + 4) * 72 + r0 + 8]);
    }
    __syncthreads();                       // s_buf now becomes P tile
    unsigned* sP = s_buf;                  // [64][36] tf32 bits

    float m0 = -1e30f, m1 = -1e30f, l0 = 0.f, l1 = 0.f;
    float of[4][4] = {};                   // O accum fragments [ntile(d)][4]

    int jbeg = c * CHUNK, jend = jbeg + CHUNK;
    for (int j0 = jbeg; j0 < jend; j0 += KT) {
        __syncthreads();
        // ---- fill KT=64 rows of K (hi/lo) and V, conflict-free STS ----
        #pragma unroll
        for (int half = 0; half < 2; half++) {
            int j = (t >> 2) + 32 * half;
            #pragma unroll
            for (int k = 0; k < 8; k++) {
                int d = (t & 3) + 4 * k;
                float kv = kptr[(size_t)d * SPA + j0 + j];
                unsigned h = to_tf32(kv);
                s_kh[j * 36 + d] = h;
                s_kl[j * 36 + d] = to_tf32(kv - __uint_as_float(h));
                s_v [j * 36 + d] = to_tf32(vptr[(size_t)d * SPA + j0 + j]);
            }
        }
        __syncthreads();

        // ---- two 32-key compute halves (no block sync between) ----
        #pragma unroll 1
        for (int half = 0; half < 2; half++) {
            int jb = half * 32;
            // ---- S = Q @ K^T via 2xTF32: Qh*Kh + Qh*Kl ----
            float sc[4][4] = {};
            #pragma unroll
            for (int ks = 0; ks < 4; ks++) {
                #pragma unroll
                for (int nt = 0; nt < 4; nt++) {
                    int kr = (jb + nt * 8 + g) * 36 + ks * 8 + tg;
                    mma_tf32(sc[nt], qh[ks], s_kh[kr], s_kh[kr + 4]);
                    mma_tf32(sc[nt], qh[ks], s_kl[kr], s_kl[kr + 4]);
                }
            }

            // ---- softmax (log2 domain) on fragments ----
            float rm0 = fmaxf(fmaxf(sc[0][0], sc[0][1]), fmaxf(sc[1][0], sc[1][1]));
            rm0 = fmaxf(rm0, fmaxf(fmaxf(sc[2][0], sc[2][1]), fmaxf(sc[3][0], sc[3][1])));
            float rm1 = fmaxf(fmaxf(sc[0][2], sc[0][3]), fmaxf(sc[1][2], sc[1][3]));
            rm1 = fmaxf(rm1, fmaxf(fmaxf(sc[2][2], sc[2][3]), fmaxf(sc[3][2], sc[3][3])));
            rm0 = fmaxf(rm0, __shfl_xor_sync(0xffffffffu, rm0, 1));
            rm0 = fmaxf(rm0, __shfl_xor_sync(0xffffffffu, rm0, 2));
            rm1 = fmaxf(rm1, __shfl_xor_sync(0xffffffffu, rm1, 1));
            rm1 = fmaxf(rm1, __shfl_xor_sync(0xffffffffu, rm1, 2));
            float nm0 = fmaxf(m0, rm0), nm1 = fmaxf(m1, rm1);
            float c0 = ex2(m0 - nm0), c1 = ex2(m1 - nm1);
            l0 *= c0; l1 *= c1;
            #pragma unroll
            for (int nt = 0; nt < 4; nt++) {
                of[nt][0] *= c0; of[nt][1] *= c0;
                of[nt][2] *= c1; of[nt][3] *= c1;
            }
            m0 = nm0; m1 = nm1;

            float ps0 = 0.f, ps1 = 0.f;
            #pragma unroll
            for (int nt = 0; nt < 4; nt++) {
                float p00 = ex2(sc[nt][0] - m0);
                float p01 = ex2(sc[nt][1] - m0);
                float p10 = ex2(sc[nt][2] - m1);
                float p11 = ex2(sc[nt][3] - m1);
                ps0 += p00 + p01; ps1 += p10 + p11;
                int col = nt * 8 + 2 * tg;
                sP[r0 * 36 + col]           = to_tf32(p00);
                sP[r0 * 36 + col + 1]       = to_tf32(p01);
                sP[(r0 + 8) * 36 + col]     = to_tf32(p10);
                sP[(r0 + 8) * 36 + col + 1] = to_tf32(p11);
            }
            l0 += ps0; l1 += ps1;
            __syncwarp();                  // warp reads only its own P rows

            // ---- O += P @ V (single tf32) ----
            #pragma unroll
            for (int ks = 0; ks < 4; ks++) {
                unsigned af[4];
                af[0] = sP[r0 * 36 + ks * 8 + tg];
                af[1] = sP[(r0 + 8) * 36 + ks * 8 + tg];
                af[2] = sP[r0 * 36 + ks * 8 + tg + 4];
                af[3] = sP[(r0 + 8) * 36 + ks * 8 + tg + 4];
                #pragma unroll
                for (int nt = 0; nt < 4; nt++) {
                    unsigned b0 = s_v[(jb + ks * 8 + tg) * 36 + nt * 8 + g];
                    unsigned b1 = s_v[(jb + ks * 8 + tg + 4) * 36 + nt * 8 + g];
                    mma_tf32(of[nt], af, b0, b1);
                }
            }
            __syncwarp();                  // P reads done before next half's writes
        }
    }

    // ---- finalize l (quad reduce) and write partials ----
    l0 += __shfl_xor_sync(0xffffffffu, l0, 1);
    l0 += __shfl_xor_sync(0xffffffffu, l0, 2);
    l1 += __shfl_xor_sync(0xffffffffu, l1, 1);
    l1 += __shfl_xor_sync(0xffffffffu, l1, 2);

    size_t base = (size_t)(b * HEADS + n) * NC + c;
    if (tg == 0) {
        g_pm[base * SPA + s0 + r0]     = m0;
        g_pl[base * SPA + s0 + r0]     = l0;
        g_pm[base * SPA + s0 + r0 + 8] = m1;
        g_pl[base * SPA + s0 + r0 + 8] = l1;
    }
    float* pa = g_pacc + base * (DHEAD * SPA);
    #pragma unroll
    for (int nt = 0; nt < 4; nt++) {
        int d0 = nt * 8 + 2 * tg;
        pa[(size_t)d0 * SPA + s0 + r0]           = of[nt][0];
        pa[(size_t)(d0 + 1) * SPA + s0 + r0]     = of[nt][1];
        pa[(size_t)d0 * SPA + s0 + r0 + 8]       = of[nt][2];
        pa[(size_t)(d0 + 1) * SPA + s0 + r0 + 8] = of[nt][3];
    }
}

// ---------------------------------------------------------------------------
// 3b) Combine split-K partials -> g_ao (m/l log2-domain)
// ---------------------------------------------------------------------------
__global__ __launch_bounds__(256) void attn_combine() {
    int t = threadIdx.x;
    int s = blockIdx.x * 256 + t;
    int yb = blockIdx.y;
    int n = yb >> 2, dbase = (yb & 3) * 8;
    int b = blockIdx.z;
    size_t base = (size_t)(b * HEADS + n) * NC;

    float pm[NC];
    float m = -1e30f;
    #pragma unroll
    for (int c = 0; c < NC; c++) {
        pm[c] = g_pm[(base + c) * SPA + s];
        m = fmaxf(m, pm[c]);
    }
    float wgt[NC];
    float L = 0.f;
    #pragma unroll
    for (int c = 0; c < NC; c++) {
        wgt[c] = ex2(fmaxf(pm[c] - m, -120.0f));
        L += g_pl[(base + c) * SPA + s] * wgt[c];
    }
    float invL = 1.0f / L;
    #pragma unroll
    for (int c = 0; c < NC; c++) wgt[c] *= invL;

    float* ao = g_ao + ((size_t)b * HTOT + n * DHEAD) * SPA;
    #pragma unroll
    for (int dd = 0; dd < 8; dd++) {
        int d = dbase + dd;
        float a = 0.f;
        #pragma unroll
        for (int c = 0; c < NC; c++)
            a += g_pacc[((base + c) * DHEAD + d) * SPA + s] * wgt[c];
        ao[(size_t)d * SPA + s] = a;
    }
}

// ---------------------------------------------------------------------------
// 4) Output projection
// ---------------------------------------------------------------------------
__global__ __launch_bounds__(256) void out_gemm(const float* __restrict__ w,
                                                const float* __restrict__ bias,
                                                float* __restrict__ y) {
    int b  = blockIdx.z;
    int m0 = blockIdx.y * BM;
    int n0 = blockIdx.x * BN;
    __shared__ float As[BM * BK];
    __shared__ float Bs[BK * BN];
    int tid = threadIdx.x;
    int tx = tid & 15, ty = tid >> 4;
    float acc[4][4] = {};
    const float* ab = g_ao + (size_t)b * HTOT * SPA;

    for (int k0 = 0; k0 < HTOT; k0 += BK) {
        for (int i = tid; i < BM * BK; i += 256) {
            int row = i / BK, col = i % BK;
            As[i] = w[(size_t)(m0 + row) * HTOT + k0 + col];
        }
        for (int i = tid; i < BK * BN; i += 256) {
            int kk = i / BN, j = i % BN;
            Bs[i] = ab[(size_t)(k0 + kk) * SPA + n0 + j];
        }
        __syncthreads();
        #pragma unroll
        for (int kk = 0; kk < BK; kk++) {
            float a[4], bb[4];
            #pragma unroll
            for (int i = 0; i < 4; i++) a[i] = As[(ty * 4 + i) * BK + kk];
            #pragma unroll
            for (int j = 0; j < 4; j++) bb[j] = Bs[kk * BN + tx * 4 + j];
            #pragma unroll
            for (int i = 0; i < 4; i++)
                #pragma unroll
                for (int j = 0; j < 4; j++) acc[i][j] += a[i] * bb[j];
        }
        __syncthreads();
    }
    #pragma unroll
    for (int i = 0; i < 4; i++) {
        float bv = bias[m0 + ty * 4 + i];
        #pragma unroll
        for (int j = 0; j < 4; j++)
            y[(size_t)(b * C_CH + m0 + ty * 4 + i) * SPA + n0 + tx * 4 + j] =
                acc[i][j] + bv;
    }
}

// ---------------------------------------------------------------------------
extern "C" void kernel_launch(void* const* d_in, const int* in_sizes, int n_in,
                              void* d_out, int out_size) {
    const float* x     = (const float*)d_in[0];
    const float* gamma = (const float*)d_in[1];
    const float* beta  = (const float*)d_in[2];
    const float* w_qkv = (const float*)d_in[3];
    const float* w_out = (const float*)d_in[4];
    const float* b_out = (const float*)d_in[5];
    float* y = (float*)d_out;

    gn_stats<<<BATCH * GROUPS, 256>>>(x);
    qkv_gemm<<<dim3(SPA / BN, QKV_R / BM, BATCH), 256>>>(x, w_qkv, gamma, beta);
    attn_partial<<<dim3(SPA / MT, HEADS * NC, BATCH), 128>>>();
    attn_combine<<<dim3(SPA / 256, HEADS * 4, BATCH), 256>>>();
    out_gemm<<<dim3(SPA / BN, C_CH / BM, BATCH), 256>>>(w_out, b_out, y);
}

// round 15
// speedup vs baseline: 1.5942x; 1.4653x over previous
#include <cuda_runtime.h>
#include <math.h>
#include <cuda_fp16.h>

#define C_CH   128
#define SPA    4096
#define BATCH  2
#define HEADS  4
#define DHEAD  32
#define GROUPS 32
#define CPG    4
#define HTOT   128
#define QKV_R  384
#define EPSV   1e-5f

#define NC     4                 // split-K chunks over keys
#define CHUNK  (SPA / NC)        // 1024 keys per chunk
#define MT     64                // queries per block
#define KT     64                // keys staged per fill (2 x 32 compute halves)

// Scratch (device globals: allocation-free per harness rules)
__device__ float g_qkv [BATCH * QKV_R * SPA];
__device__ float g_ao  [BATCH * HTOT * SPA];
__device__ float g_mean[BATCH * GROUPS];
__device__ float g_rstd[BATCH * GROUPS];
__device__ float g_pacc[BATCH * HEADS * NC * DHEAD * SPA];
__device__ float g_pm  [BATCH * HEADS * NC * SPA];
__device__ float g_pl  [BATCH * HEADS * NC * SPA];

__device__ __forceinline__ float ex2(float x) {
    float r; asm("ex2.approx.ftz.f32 %0, %1;" : "=f"(r) : "f"(x)); return r;
}
// pack two floats into f16x2: lo -> lower half, hi -> upper half
__device__ __forceinline__ unsigned pack_h2(float lo, float hi) {
    unsigned r; asm("cvt.rn.f16x2.f32 %0, %1, %2;" : "=r"(r) : "f"(hi), "f"(lo));
    return r;
}
// D += A(16x16,row) * B(16x8,col) ; f16 operands, f32 accum
__device__ __forceinline__ void mma_f16(float* c, const unsigned* a,
                                        unsigned b0, unsigned b1) {
    asm volatile(
        "mma.sync.aligned.m16n8k16.row.col.f32.f16.f16.f32 "
        "{%0,%1,%2,%3}, {%4,%5,%6,%7}, {%8,%9}, {%0,%1,%2,%3};"
        : "+f"(c[0]), "+f"(c[1]), "+f"(c[2]), "+f"(c[3])
        : "r"(a[0]), "r"(a[1]), "r"(a[2]), "r"(a[3]), "r"(b0), "r"(b1));
}

// ---------------------------------------------------------------------------
// 1) GroupNorm statistics
// ---------------------------------------------------------------------------
__global__ __launch_bounds__(256) void gn_stats(const float* __restrict__ x) {
    int bg = blockIdx.x;
    const float* p = x + (size_t)bg * (CPG * SPA);
    float s1 = 0.f, s2 = 0.f;
    for (int i = threadIdx.x; i < CPG * SPA; i += 256) {
        float v = p[i];
        s1 += v; s2 += v * v;
    }
    __shared__ float r1[8], r2[8];
    #pragma unroll
    for (int o = 16; o; o >>= 1) {
        s1 += __shfl_down_sync(0xffffffffu, s1, o);
        s2 += __shfl_down_sync(0xffffffffu, s2, o);
    }
    int w = threadIdx.x >> 5, l = threadIdx.x & 31;
    if (l == 0) { r1[w] = s1; r2[w] = s2; }
    __syncthreads();
    if (w == 0) {
        s1 = (l < 8) ? r1[l] : 0.f;
        s2 = (l < 8) ? r2[l] : 0.f;
        #pragma unroll
        for (int o = 4; o; o >>= 1) {
            s1 += __shfl_down_sync(0xffffffffu, s1, o);
            s2 += __shfl_down_sync(0xffffffffu, s2, o);
        }
        if (l == 0) {
            const float invN = 1.0f / (CPG * SPA);
            float mean = s1 * invN;
            float var  = s2 * invN - mean * mean;
            g_mean[bg] = mean;
            g_rstd[bg] = rsqrtf(var + EPSV);
        }
    }
}

// ---------------------------------------------------------------------------
// 2) QKV GEMM with fused GroupNorm on the activation load
// ---------------------------------------------------------------------------
#define BM 64
#define BN 64
#define BK 32

__global__ __launch_bounds__(256) void qkv_gemm(const float* __restrict__ x,
                                                const float* __restrict__ w,
                                                const float* __restrict__ gamma,
                                                const float* __restrict__ beta) {
    int b  = blockIdx.z;
    int m0 = blockIdx.y * BM;
    int n0 = blockIdx.x * BN;
    __shared__ float As[BM * BK];
    __shared__ float Bs[BK * BN];
    int tid = threadIdx.x;
    int tx = tid & 15, ty = tid >> 4;
    float acc[4][4] = {};
    const float* xb = x + (size_t)b * C_CH * SPA;

    for (int k0 = 0; k0 < C_CH; k0 += BK) {
        for (int i = tid; i < BM * BK; i += 256) {
            int row = i / BK, col = i % BK;
            As[i] = w[(size_t)(m0 + row) * C_CH + k0 + col];
        }
        for (int i = tid; i < BK * BN; i += 256) {
            int kk = i / BN, j = i % BN;
            int c = k0 + kk;
            int g = c >> 2;
            float mv = g_mean[b * GROUPS + g];
            float rs = g_rstd[b * GROUPS + g];
            float v = xb[(size_t)c * SPA + n0 + j];
            Bs[i] = (v - mv) * rs * gamma[c] + beta[c];
        }
        __syncthreads();
        #pragma unroll
        for (int kk = 0; kk < BK; kk++) {
            float a[4], bb[4];
            #pragma unroll
            for (int i = 0; i < 4; i++) a[i] = As[(ty * 4 + i) * BK + kk];
            #pragma unroll
            for (int j = 0; j < 4; j++) bb[j] = Bs[kk * BN + tx * 4 + j];
            #pragma unroll
            for (int i = 0; i < 4; i++)
                #pragma unroll
                for (int j = 0; j < 4; j++) acc[i][j] += a[i] * bb[j];
        }
        __syncthreads();
    }
    float* outb = g_qkv + (size_t)b * QKV_R * SPA;
    #pragma unroll
    for (int i = 0; i < 4; i++)
        #pragma unroll
        for (int j = 0; j < 4; j++)
            outb[(size_t)(m0 + ty * 4 + i) * SPA + n0 + tx * 4 + j] = acc[i][j];
}

// ---------------------------------------------------------------------------
// 3a) Flash attention partial — fp16 mma.sync m16n8k16.
//     QK: Q single fp16 x K (hi+lo fp16 split) = 16 mmas/half.
//     PV: P,V single fp16 = 8 mmas/half. (was 48 tf32-k8 mmas/half)
//     KT=64 keys staged per fill, computed as 2x32 halves.
//     Grid: (64, HEADS*NC=16, 2) = 2048 blocks of 128 threads.
// ---------------------------------------------------------------------------
__global__ __launch_bounds__(128) void attn_partial() {
    int qt = blockIdx.x;
    int yc = blockIdx.y;
    int b  = blockIdx.z;
    int n  = yc >> 2, c = yc & (NC - 1);
    int t  = threadIdx.x;
    int w  = t >> 5, lane = t & 31;
    int g  = lane >> 2, tg = lane & 3;     // mma fragment coords
    int r0 = w * 16 + g;                   // this thread's first q-row (of 2)

    // smem: s_buf = Q stage [32][72] f32, then reused as P tile [64][20] h2
    __shared__ __align__(16) unsigned s_buf[2304];
    __shared__ __align__(16) unsigned s_kh[KT * 20];   // [key][d-pair] f16x2 hi
    __shared__ __align__(16) unsigned s_kl[KT * 20];   // [key][d-pair] f16x2 lo
    __shared__ __align__(16) unsigned s_v [32 * 36];   // [d][key-pair] f16x2

    const float* qkv_b = g_qkv + (size_t)b * QKV_R * SPA;
    const float* qptr = qkv_b + (size_t)(n * DHEAD) * SPA;
    const float* kptr = qkv_b + (size_t)(HTOT + n * DHEAD) * SPA;
    const float* vptr = qkv_b + (size_t)(2 * HTOT + n * DHEAD) * SPA;
    int s0 = qt * MT;

    const float scale2 = 0.17677669529663687f * 1.4426950408889634f; // /sqrt(32)*log2e

    // ---- stage Q (scaled f32) as [d][72], coalesced + conflict-free ----
    float* sQ = (float*)s_buf;
    for (int idx = t; idx < MT * DHEAD; idx += 128) {
        int d = idx >> 6, row = idx & 63;
        sQ[d * 72 + row] = qptr[(size_t)d * SPA + s0 + row] * scale2;
    }
    __syncthreads();

    // ---- Q fragments (fp16, packed pairs along d): 2 k16-groups ----
    // a0:[r0][2tg,2tg+1], a1:[r0+8][..], a2:[r0][+8], a3:[r0+8][+8]
    unsigned qa[2][4];
    #pragma unroll
    for (int ks = 0; ks < 2; ks++) {
        int d = 16 * ks + 2 * tg;
        qa[ks][0] = pack_h2(sQ[d * 72 + r0],       sQ[(d + 1) * 72 + r0]);
        qa[ks][1] = pack_h2(sQ[d * 72 + r0 + 8],   sQ[(d + 1) * 72 + r0 + 8]);
        qa[ks][2] = pack_h2(sQ[(d + 8) * 72 + r0], sQ[(d + 9) * 72 + r0]);
        qa[ks][3] = pack_h2(sQ[(d + 8) * 72 + r0 + 8], sQ[(d + 9) * 72 + r0 + 8]);
    }
    __syncthreads();                       // s_buf now becomes P tile
    unsigned* sP = s_buf;                  // [64][20] f16x2 (key pairs)

    float m0 = -1e30f, m1 = -1e30f, l0 = 0.f, l1 = 0.f;
    float of[4][4] = {};                   // O accum fragments [ntile(d)][4]

    int jbeg = c * CHUNK, jend = jbeg + CHUNK;
    for (int j0 = jbeg; j0 < jend; j0 += KT) {
        __syncthreads();
        // ---- fill K: [key][d2] hi/lo f16x2 (d pairs), stride 20 ----
        #pragma unroll
        for (int half = 0; half < 2; half++) {
            int j = (t >> 2) + 32 * half;
            #pragma unroll
            for (int k = 0; k < 4; k++) {
                int d2 = (t & 3) + 4 * k;
                int d = 2 * d2;
                float kv0 = kptr[(size_t)d * SPA + j0 + j];
                float kv1 = kptr[(size_t)(d + 1) * SPA + j0 + j];
                float h0 = __half2float(__float2half_rn(kv0));
                float h1 = __half2float(__float2half_rn(kv1));
                s_kh[j * 20 + d2] = pack_h2(h0, h1);
                s_kl[j * 20 + d2] = pack_h2(kv0 - h0, kv1 - h1);
            }
        }
        // ---- fill V: [d][key-pair] f16x2, stride 36 (float2 gmem loads) ----
        {
            int d = t >> 2;
            #pragma unroll
            for (int k = 0; k < 8; k++) {
                int j2 = (t & 3) + 4 * k;
                float2 vv = *(const float2*)&vptr[(size_t)d * SPA + j0 + 2 * j2];
                s_v[d * 36 + j2] = pack_h2(vv.x, vv.y);
            }
        }
        __syncthreads();

        // ---- two 32-key compute halves (no block sync between) ----
        #pragma unroll 1
        for (int half = 0; half < 2; half++) {
            int jb = half * 32;
            // ---- S = Q @ K^T : fp16, K hi + K lo ----
            float sc[4][4] = {};
            #pragma unroll
            for (int ks = 0; ks < 2; ks++) {
                #pragma unroll
                for (int nt = 0; nt < 4; nt++) {
                    int kr = (jb + nt * 8 + g) * 20 + 8 * ks + tg;
                    mma_f16(sc[nt], qa[ks], s_kh[kr], s_kh[kr + 4]);
                    mma_f16(sc[nt], qa[ks], s_kl[kr], s_kl[kr + 4]);
                }
            }

            // ---- softmax (log2 domain) on fragments ----
            float rm0 = fmaxf(fmaxf(sc[0][0], sc[0][1]), fmaxf(sc[1][0], sc[1][1]));
            rm0 = fmaxf(rm0, fmaxf(fmaxf(sc[2][0], sc[2][1]), fmaxf(sc[3][0], sc[3][1])));
            float rm1 = fmaxf(fmaxf(sc[0][2], sc[0][3]), fmaxf(sc[1][2], sc[1][3]));
            rm1 = fmaxf(rm1, fmaxf(fmaxf(sc[2][2], sc[2][3]), fmaxf(sc[3][2], sc[3][3])));
            rm0 = fmaxf(rm0, __shfl_xor_sync(0xffffffffu, rm0, 1));
            rm0 = fmaxf(rm0, __shfl_xor_sync(0xffffffffu, rm0, 2));
            rm1 = fmaxf(rm1, __shfl_xor_sync(0xffffffffu, rm1, 1));
            rm1 = fmaxf(rm1, __shfl_xor_sync(0xffffffffu, rm1, 2));
            float nm0 = fmaxf(m0, rm0), nm1 = fmaxf(m1, rm1);
            float c0 = ex2(m0 - nm0), c1 = ex2(m1 - nm1);
            l0 *= c0; l1 *= c1;
            #pragma unroll
            for (int nt = 0; nt < 4; nt++) {
                of[nt][0] *= c0; of[nt][1] *= c0;
                of[nt][2] *= c1; of[nt][3] *= c1;
            }
            m0 = nm0; m1 = nm1;

            float ps0 = 0.f, ps1 = 0.f;
            #pragma unroll
            for (int nt = 0; nt < 4; nt++) {
                float p00 = ex2(sc[nt][0] - m0);
                float p01 = ex2(sc[nt][1] - m0);
                float p10 = ex2(sc[nt][2] - m1);
                float p11 = ex2(sc[nt][3] - m1);
                ps0 += p00 + p01; ps1 += p10 + p11;
                int cw = nt * 4 + tg;      // key-pair word index
                sP[r0 * 20 + cw]       = pack_h2(p00, p01);
                sP[(r0 + 8) * 20 + cw] = pack_h2(p10, p11);
            }
            l0 += ps0; l1 += ps1;
            __syncwarp();                  // warp reads only its own P rows

            // ---- O += P @ V (fp16): 2 k16-groups over the 32 keys ----
            #pragma unroll
            for (int ks = 0; ks < 2; ks++) {
                unsigned af[4];
                af[0] = sP[r0 * 20 + 8 * ks + tg];
                af[1] = sP[(r0 + 8) * 20 + 8 * ks + tg];
                af[2] = sP[r0 * 20 + 8 * ks + tg + 4];
                af[3] = sP[(r0 + 8) * 20 + 8 * ks + tg + 4];
                int kp = (jb >> 1) + 8 * ks + tg;   // global key-pair index
                #pragma unroll
                for (int nt = 0; nt < 4; nt++) {
                    unsigned b0 = s_v[(nt * 8 + g) * 36 + kp];
                    unsigned b1 = s_v[(nt * 8 + g) * 36 + kp + 4];
                    mma_f16(of[nt], af, b0, b1);
                }
            }
            __syncwarp();                  // P reads done before next half's writes
        }
    }

    // ---- finalize l (quad reduce) and write partials ----
    l0 += __shfl_xor_sync(0xffffffffu, l0, 1);
    l0 += __shfl_xor_sync(0xffffffffu, l0, 2);
    l1 += __shfl_xor_sync(0xffffffffu, l1, 1);
    l1 += __shfl_xor_sync(0xffffffffu, l1, 2);

    size_t base = (size_t)(b * HEADS + n) * NC + c;
    if (tg == 0) {
        g_pm[base * SPA + s0 + r0]     = m0;
        g_pl[base * SPA + s0 + r0]     = l0;
        g_pm[base * SPA + s0 + r0 + 8] = m1;
        g_pl[base * SPA + s0 + r0 + 8] = l1;
    }
    float* pa = g_pacc + base * (DHEAD * SPA);
    #pragma unroll
    for (int nt = 0; nt < 4; nt++) {
        int d0 = nt * 8 + 2 * tg;
        pa[(size_t)d0 * SPA + s0 + r0]           = of[nt][0];
        pa[(size_t)(d0 + 1) * SPA + s0 + r0]     = of[nt][1];
        pa[(size_t)d0 * SPA + s0 + r0 + 8]       = of[nt][2];
        pa[(size_t)(d0 + 1) * SPA + s0 + r0 + 8] = of[nt][3];
    }
}

// ---------------------------------------------------------------------------
// 3b) Combine split-K partials -> g_ao (m/l log2-domain)
// ---------------------------------------------------------------------------
__global__ __launch_bounds__(256) void attn_combine() {
    int t = threadIdx.x;
    int s = blockIdx.x * 256 + t;
    int yb = blockIdx.y;
    int n = yb >> 2, dbase = (yb & 3) * 8;
    int b = blockIdx.z;
    size_t base = (size_t)(b * HEADS + n) * NC;

    float pm[NC];
    float m = -1e30f;
    #pragma unroll
    for (int c = 0; c < NC; c++) {
        pm[c] = g_pm[(base + c) * SPA + s];
        m = fmaxf(m, pm[c]);
    }
    float wgt[NC];
    float L = 0.f;
    #pragma unroll
    for (int c = 0; c < NC; c++) {
        wgt[c] = ex2(fmaxf(pm[c] - m, -120.0f));
        L += g_pl[(base + c) * SPA + s] * wgt[c];
    }
    float invL = 1.0f / L;
    #pragma unroll
    for (int c = 0; c < NC; c++) wgt[c] *= invL;

    float* ao = g_ao + ((size_t)b * HTOT + n * DHEAD) * SPA;
    #pragma unroll
    for (int dd = 0; dd < 8; dd++) {
        int d = dbase + dd;
        float a = 0.f;
        #pragma unroll
        for (int c = 0; c < NC; c++)
            a += g_pacc[((base + c) * DHEAD + d) * SPA + s] * wgt[c];
        ao[(size_t)d * SPA + s] = a;
    }
}

// ---------------------------------------------------------------------------
// 4) Output projection
// ---------------------------------------------------------------------------
__global__ __launch_bounds__(256) void out_gemm(const float* __restrict__ w,
                                                const float* __restrict__ bias,
                                                float* __restrict__ y) {
    int b  = blockIdx.z;
    int m0 = blockIdx.y * BM;
    int n0 = blockIdx.x * BN;
    __shared__ float As[BM * BK];
    __shared__ float Bs[BK * BN];
    int tid = threadIdx.x;
    int tx = tid & 15, ty = tid >> 4;
    float acc[4][4] = {};
    const float* ab = g_ao + (size_t)b * HTOT * SPA;

    for (int k0 = 0; k0 < HTOT; k0 += BK) {
        for (int i = tid; i < BM * BK; i += 256) {
            int row = i / BK, col = i % BK;
            As[i] = w[(size_t)(m0 + row) * HTOT + k0 + col];
        }
        for (int i = tid; i < BK * BN; i += 256) {
            int kk = i / BN, j = i % BN;
            Bs[i] = ab[(size_t)(k0 + kk) * SPA + n0 + j];
        }
        __syncthreads();
        #pragma unroll
        for (int kk = 0; kk < BK; kk++) {
            float a[4], bb[4];
            #pragma unroll
            for (int i = 0; i < 4; i++) a[i] = As[(ty * 4 + i) * BK + kk];
            #pragma unroll
            for (int j = 0; j < 4; j++) bb[j] = Bs[kk * BN + tx * 4 + j];
            #pragma unroll
            for (int i = 0; i < 4; i++)
                #pragma unroll
                for (int j = 0; j < 4; j++) acc[i][j] += a[i] * bb[j];
        }
        __syncthreads();
    }
    #pragma unroll
    for (int i = 0; i < 4; i++) {
        float bv = bias[m0 + ty * 4 + i];
        #pragma unroll
        for (int j = 0; j < 4; j++)
            y[(size_t)(b * C_CH + m0 + ty * 4 + i) * SPA + n0 + tx * 4 + j] =
                acc[i][j] + bv;
    }
}

// ---------------------------------------------------------------------------
extern "C" void kernel_launch(void* const* d_in, const int* in_sizes, int n_in,
                              void* d_out, int out_size) {
    const float* x     = (const float*)d_in[0];
    const float* gamma = (const float*)d_in[1];
    const float* beta  = (const float*)d_in[2];
    const float* w_qkv = (const float*)d_in[3];
    const float* w_out = (const float*)d_in[4];
    const float* b_out = (const float*)d_in[5];
    float* y = (float*)d_out;

    gn_stats<<<BATCH * GROUPS, 256>>>(x);
    qkv_gemm<<<dim3(SPA / BN, QKV_R / BM, BATCH), 256>>>(x, w_qkv, gamma, beta);
    attn_partial<<<dim3(SPA / MT, HEADS * NC, BATCH), 128>>>();
    attn_combine<<<dim3(SPA / 256, HEADS * 4, BATCH), 256>>>();
    out_gemm<<<dim3(SPA / BN, C_CH / BM, BATCH), 256>>>(w_out, b_out, y);
}

// round 16
// speedup vs baseline: 1.7076x; 1.0712x over previous
#include <cuda_runtime.h>
#include <math.h>
#include <cuda_fp16.h>

#define C_CH   128
#define SPA    4096
#define BATCH  2
#define HEADS  4
#define DHEAD  32
#define GROUPS 32
#define CPG    4
#define HTOT   128
#define QKV_R  384
#define EPSV   1e-5f

#define NC     4                 // split-K chunks over keys
#define CHUNK  (SPA / NC)        // 1024 keys per chunk
#define MT     64                // queries per block
#define KT     64                // keys staged per fill (2 x 32 compute halves)

// Scratch (device globals: allocation-free per harness rules)
__device__ float g_qkv [BATCH * QKV_R * SPA];
__device__ float g_ao  [BATCH * HTOT * SPA];
__device__ float g_mean[BATCH * GROUPS];
__device__ float g_rstd[BATCH * GROUPS];
__device__ float g_pacc[BATCH * HEADS * NC * DHEAD * SPA];
__device__ float g_pm  [BATCH * HEADS * NC * SPA];
__device__ float g_pl  [BATCH * HEADS * NC * SPA];

__device__ __forceinline__ float ex2(float x) {
    float r; asm("ex2.approx.ftz.f32 %0, %1;" : "=f"(r) : "f"(x)); return r;
}
// pack two floats into f16x2: first arg -> lower half
__device__ __forceinline__ unsigned pack_h2(float lo, float hi) {
    unsigned r; asm("cvt.rn.f16x2.f32 %0, %1, %2;" : "=r"(r) : "f"(hi), "f"(lo));
    return r;
}
// D += A(16x16,row) * B(16x8,col) ; f16 operands, f32 accum
__device__ __forceinline__ void mma_f16(float* c, const unsigned* a,
                                        unsigned b0, unsigned b1) {
    asm volatile(
        "mma.sync.aligned.m16n8k16.row.col.f32.f16.f16.f32 "
        "{%0,%1,%2,%3}, {%4,%5,%6,%7}, {%8,%9}, {%0,%1,%2,%3};"
        : "+f"(c[0]), "+f"(c[1]), "+f"(c[2]), "+f"(c[3])
        : "r"(a[0]), "r"(a[1]), "r"(a[2]), "r"(a[3]), "r"(b0), "r"(b1));
}

// ---------------------------------------------------------------------------
// 1) GroupNorm statistics
// ---------------------------------------------------------------------------
__global__ __launch_bounds__(256) void gn_stats(const float* __restrict__ x) {
    int bg = blockIdx.x;
    const float* p = x + (size_t)bg * (CPG * SPA);
    float s1 = 0.f, s2 = 0.f;
    for (int i = threadIdx.x; i < CPG * SPA; i += 256) {
        float v = p[i];
        s1 += v; s2 += v * v;
    }
    __shared__ float r1[8], r2[8];
    #pragma unroll
    for (int o = 16; o; o >>= 1) {
        s1 += __shfl_down_sync(0xffffffffu, s1, o);
        s2 += __shfl_down_sync(0xffffffffu, s2, o);
    }
    int w = threadIdx.x >> 5, l = threadIdx.x & 31;
    if (l == 0) { r1[w] = s1; r2[w] = s2; }
    __syncthreads();
    if (w == 0) {
        s1 = (l < 8) ? r1[l] : 0.f;
        s2 = (l < 8) ? r2[l] : 0.f;
        #pragma unroll
        for (int o = 4; o; o >>= 1) {
            s1 += __shfl_down_sync(0xffffffffu, s1, o);
            s2 += __shfl_down_sync(0xffffffffu, s2, o);
        }
        if (l == 0) {
            const float invN = 1.0f / (CPG * SPA);
            float mean = s1 * invN;
            float var  = s2 * invN - mean * mean;
            g_mean[bg] = mean;
            g_rstd[bg] = rsqrtf(var + EPSV);
        }
    }
}

// ---------------------------------------------------------------------------
// 2) QKV GEMM with fused GroupNorm on the activation load
// ---------------------------------------------------------------------------
#define BM 64
#define BN 64
#define BK 32

__global__ __launch_bounds__(256) void qkv_gemm(const float* __restrict__ x,
                                                const float* __restrict__ w,
                                                const float* __restrict__ gamma,
                                                const float* __restrict__ beta) {
    int b  = blockIdx.z;
    int m0 = blockIdx.y * BM;
    int n0 = blockIdx.x * BN;
    __shared__ float As[BM * BK];
    __shared__ float Bs[BK * BN];
    int tid = threadIdx.x;
    int tx = tid & 15, ty = tid >> 4;
    float acc[4][4] = {};
    const float* xb = x + (size_t)b * C_CH * SPA;

    for (int k0 = 0; k0 < C_CH; k0 += BK) {
        for (int i = tid; i < BM * BK; i += 256) {
            int row = i / BK, col = i % BK;
            As[i] = w[(size_t)(m0 + row) * C_CH + k0 + col];
        }
        for (int i = tid; i < BK * BN; i += 256) {
            int kk = i / BN, j = i % BN;
            int c = k0 + kk;
            int g = c >> 2;
            float mv = g_mean[b * GROUPS + g];
            float rs = g_rstd[b * GROUPS + g];
            float v = xb[(size_t)c * SPA + n0 + j];
            Bs[i] = (v - mv) * rs * gamma[c] + beta[c];
        }
        __syncthreads();
        #pragma unroll
        for (int kk = 0; kk < BK; kk++) {
            float a[4], bb[4];
            #pragma unroll
            for (int i = 0; i < 4; i++) a[i] = As[(ty * 4 + i) * BK + kk];
            #pragma unroll
            for (int j = 0; j < 4; j++) bb[j] = Bs[kk * BN + tx * 4 + j];
            #pragma unroll
            for (int i = 0; i < 4; i++)
                #pragma unroll
                for (int j = 0; j < 4; j++) acc[i][j] += a[i] * bb[j];
        }
        __syncthreads();
    }
    float* outb = g_qkv + (size_t)b * QKV_R * SPA;
    #pragma unroll
    for (int i = 0; i < 4; i++)
        #pragma unroll
        for (int j = 0; j < 4; j++)
            outb[(size_t)(m0 + ty * 4 + i) * SPA + n0 + tx * 4 + j] = acc[i][j];
}

// ---------------------------------------------------------------------------
// 3a) Flash attention partial — fp16 mma.sync m16n8k16, REGISTER-DIRECT P.
//     QK C-fragment maps directly onto PV A-fragment (thread-local): no P
//     smem roundtrip, no extra syncs. QK: Q fp16 x K hi/lo (16 mmas/half).
//     PV: 8 mmas/half. KT=64 keys staged per fill, 2x32 compute halves.
//     Grid: (64, HEADS*NC=16, 2) = 2048 blocks of 128 threads.
// ---------------------------------------------------------------------------
__global__ __launch_bounds__(128) void attn_partial() {
    int qt = blockIdx.x;
    int yc = blockIdx.y;
    int b  = blockIdx.z;
    int n  = yc >> 2, c = yc & (NC - 1);
    int t  = threadIdx.x;
    int w  = t >> 5, lane = t & 31;
    int g  = lane >> 2, tg = lane & 3;     // mma fragment coords
    int r0 = w * 16 + g;                   // this thread's first q-row (of 2)

    // smem: Q stage [32][72] f32 (only used during prologue)
    __shared__ __align__(16) float sQ[2304];
    __shared__ __align__(16) unsigned s_kh[KT * 20];   // [key][d-pair] f16x2 hi
    __shared__ __align__(16) unsigned s_kl[KT * 20];   // [key][d-pair] f16x2 lo
    __shared__ __align__(16) unsigned s_v [32 * 36];   // [d][key-pair] f16x2

    const float* qkv_b = g_qkv + (size_t)b * QKV_R * SPA;
    const float* qptr = qkv_b + (size_t)(n * DHEAD) * SPA;
    const float* kptr = qkv_b + (size_t)(HTOT + n * DHEAD) * SPA;
    const float* vptr = qkv_b + (size_t)(2 * HTOT + n * DHEAD) * SPA;
    int s0 = qt * MT;

    const float scale2 = 0.17677669529663687f * 1.4426950408889634f; // /sqrt(32)*log2e

    // ---- stage Q (scaled f32) as [d][72], coalesced + conflict-free ----
    for (int idx = t; idx < MT * DHEAD; idx += 128) {
        int d = idx >> 6, row = idx & 63;
        sQ[d * 72 + row] = qptr[(size_t)d * SPA + s0 + row] * scale2;
    }
    __syncthreads();

    // ---- Q fragments (fp16, packed pairs along d): 2 k16-groups ----
    unsigned qa[2][4];
    #pragma unroll
    for (int ks = 0; ks < 2; ks++) {
        int d = 16 * ks + 2 * tg;
        qa[ks][0] = pack_h2(sQ[d * 72 + r0],       sQ[(d + 1) * 72 + r0]);
        qa[ks][1] = pack_h2(sQ[d * 72 + r0 + 8],   sQ[(d + 1) * 72 + r0 + 8]);
        qa[ks][2] = pack_h2(sQ[(d + 8) * 72 + r0], sQ[(d + 9) * 72 + r0]);
        qa[ks][3] = pack_h2(sQ[(d + 8) * 72 + r0 + 8], sQ[(d + 9) * 72 + r0 + 8]);
    }

    float m0 = -1e30f, m1 = -1e30f, l0 = 0.f, l1 = 0.f;
    float of[4][4] = {};                   // O accum fragments [ntile(d)][4]

    int jbeg = c * CHUNK, jend = jbeg + CHUNK;
    for (int j0 = jbeg; j0 < jend; j0 += KT) {
        __syncthreads();
        // ---- fill K: [key][d2] hi/lo f16x2 (d pairs), stride 20 ----
        #pragma unroll
        for (int half = 0; half < 2; half++) {
            int j = (t >> 2) + 32 * half;
            #pragma unroll
            for (int k = 0; k < 4; k++) {
                int d2 = (t & 3) + 4 * k;
                int d = 2 * d2;
                float kv0 = kptr[(size_t)d * SPA + j0 + j];
                float kv1 = kptr[(size_t)(d + 1) * SPA + j0 + j];
                float h0 = __half2float(__float2half_rn(kv0));
                float h1 = __half2float(__float2half_rn(kv1));
                s_kh[j * 20 + d2] = pack_h2(h0, h1);
                s_kl[j * 20 + d2] = pack_h2(kv0 - h0, kv1 - h1);
            }
        }
        // ---- fill V: [d][key-pair] f16x2, stride 36 (float2 gmem loads) ----
        {
            int d = t >> 2;
            #pragma unroll
            for (int k = 0; k < 8; k++) {
                int j2 = (t & 3) + 4 * k;
                float2 vv = *(const float2*)&vptr[(size_t)d * SPA + j0 + 2 * j2];
                s_v[d * 36 + j2] = pack_h2(vv.x, vv.y);
            }
        }
        __syncthreads();

        // ---- two 32-key compute halves (no block sync between) ----
        #pragma unroll 1
        for (int half = 0; half < 2; half++) {
            int jb = half * 32;
            // ---- S = Q @ K^T : fp16, K hi + K lo ----
            float sc[4][4] = {};
            #pragma unroll
            for (int ks = 0; ks < 2; ks++) {
                #pragma unroll
                for (int nt = 0; nt < 4; nt++) {
                    int kr = (jb + nt * 8 + g) * 20 + 8 * ks + tg;
                    mma_f16(sc[nt], qa[ks], s_kh[kr], s_kh[kr + 4]);
                    mma_f16(sc[nt], qa[ks], s_kl[kr], s_kl[kr + 4]);
                }
            }

            // ---- softmax (log2 domain) on fragments ----
            float rm0 = fmaxf(fmaxf(sc[0][0], sc[0][1]), fmaxf(sc[1][0], sc[1][1]));
            rm0 = fmaxf(rm0, fmaxf(fmaxf(sc[2][0], sc[2][1]), fmaxf(sc[3][0], sc[3][1])));
            float rm1 = fmaxf(fmaxf(sc[0][2], sc[0][3]), fmaxf(sc[1][2], sc[1][3]));
            rm1 = fmaxf(rm1, fmaxf(fmaxf(sc[2][2], sc[2][3]), fmaxf(sc[3][2], sc[3][3])));
            rm0 = fmaxf(rm0, __shfl_xor_sync(0xffffffffu, rm0, 1));
            rm0 = fmaxf(rm0, __shfl_xor_sync(0xffffffffu, rm0, 2));
            rm1 = fmaxf(rm1, __shfl_xor_sync(0xffffffffu, rm1, 1));
            rm1 = fmaxf(rm1, __shfl_xor_sync(0xffffffffu, rm1, 2));
            float nm0 = fmaxf(m0, rm0), nm1 = fmaxf(m1, rm1);
            float c0 = ex2(m0 - nm0), c1 = ex2(m1 - nm1);
            l0 *= c0; l1 *= c1;
            #pragma unroll
            for (int nt = 0; nt < 4; nt++) {
                of[nt][0] *= c0; of[nt][1] *= c0;
                of[nt][2] *= c1; of[nt][3] *= c1;
            }
            m0 = nm0; m1 = nm1;

            // P values per tile nt (rows r0, r0+8; cols 2tg, 2tg+1)
            float p[4][4];
            float ps0 = 0.f, ps1 = 0.f;
            #pragma unroll
            for (int nt = 0; nt < 4; nt++) {
                p[nt][0] = ex2(sc[nt][0] - m0);
                p[nt][1] = ex2(sc[nt][1] - m0);
                p[nt][2] = ex2(sc[nt][2] - m1);
                p[nt][3] = ex2(sc[nt][3] - m1);
                ps0 += p[nt][0] + p[nt][1];
                ps1 += p[nt][2] + p[nt][3];
            }
            l0 += ps0; l1 += ps1;

            // ---- O += P @ V : REGISTER-DIRECT A-fragment from p[][] ----
            // k-group ks covers QK tiles 2ks (keys 16ks+2tg..) and 2ks+1 (+8)
            #pragma unroll
            for (int ks = 0; ks < 2; ks++) {
                unsigned af[4];
                af[0] = pack_h2(p[2 * ks][0],     p[2 * ks][1]);
                af[1] = pack_h2(p[2 * ks][2],     p[2 * ks][3]);
                af[2] = pack_h2(p[2 * ks + 1][0], p[2 * ks + 1][1]);
                af[3] = pack_h2(p[2 * ks + 1][2], p[2 * ks + 1][3]);
                int kp = (jb >> 1) + 8 * ks + tg;   // global key-pair index
                #pragma unroll
                for (int nt = 0; nt < 4; nt++) {
                    unsigned b0 = s_v[(nt * 8 + g) * 36 + kp];
                    unsigned b1 = s_v[(nt * 8 + g) * 36 + kp + 4];
                    mma_f16(of[nt], af, b0, b1);
                }
            }
        }
    }

    // ---- finalize l (quad reduce) and write partials ----
    l0 += __shfl_xor_sync(0xffffffffu, l0, 1);
    l0 += __shfl_xor_sync(0xffffffffu, l0, 2);
    l1 += __shfl_xor_sync(0xffffffffu, l1, 1);
    l1 += __shfl_xor_sync(0xffffffffu, l1, 2);

    size_t base = (size_t)(b * HEADS + n) * NC + c;
    if (tg == 0) {
        g_pm[base * SPA + s0 + r0]     = m0;
        g_pl[base * SPA + s0 + r0]     = l0;
        g_pm[base * SPA + s0 + r0 + 8] = m1;
        g_pl[base * SPA + s0 + r0 + 8] = l1;
    }
    float* pa = g_pacc + base * (DHEAD * SPA);
    #pragma unroll
    for (int nt = 0; nt < 4; nt++) {
        int d0 = nt * 8 + 2 * tg;
        pa[(size_t)d0 * SPA + s0 + r0]           = of[nt][0];
        pa[(size_t)(d0 + 1) * SPA + s0 + r0]     = of[nt][1];
        pa[(size_t)d0 * SPA + s0 + r0 + 8]       = of[nt][2];
        pa[(size_t)(d0 + 1) * SPA + s0 + r0 + 8] = of[nt][3];
    }
}

// ---------------------------------------------------------------------------
// 3b) Combine split-K partials -> g_ao (m/l log2-domain)
// ---------------------------------------------------------------------------
__global__ __launch_bounds__(256) void attn_combine() {
    int t = threadIdx.x;
    int s = blockIdx.x * 256 + t;
    int yb = blockIdx.y;
    int n = yb >> 2, dbase = (yb & 3) * 8;
    int b = blockIdx.z;
    size_t base = (size_t)(b * HEADS + n) * NC;

    float pm[NC];
    float m = -1e30f;
    #pragma unroll
    for (int c = 0; c < NC; c++) {
        pm[c] = g_pm[(base + c) * SPA + s];
        m = fmaxf(m, pm[c]);
    }
    float wgt[NC];
    float L = 0.f;
    #pragma unroll
    for (int c = 0; c < NC; c++) {
        wgt[c] = ex2(fmaxf(pm[c] - m, -120.0f));
        L += g_pl[(base + c) * SPA + s] * wgt[c];
    }
    float invL = 1.0f / L;
    #pragma unroll
    for (int c = 0; c < NC; c++) wgt[c] *= invL;

    float* ao = g_ao + ((size_t)b * HTOT + n * DHEAD) * SPA;
    #pragma unroll
    for (int dd = 0; dd < 8; dd++) {
        int d = dbase + dd;
        float a = 0.f;
        #pragma unroll
        for (int c = 0; c < NC; c++)
            a += g_pacc[((base + c) * DHEAD + d) * SPA + s] * wgt[c];
        ao[(size_t)d * SPA + s] = a;
    }
}

// ---------------------------------------------------------------------------
// 4) Output projection
// ---------------------------------------------------------------------------
__global__ __launch_bounds__(256) void out_gemm(const float* __restrict__ w,
                                                const float* __restrict__ bias,
                                                float* __restrict__ y) {
    int b  = blockIdx.z;
    int m0 = blockIdx.y * BM;
    int n0 = blockIdx.x * BN;
    __shared__ float As[BM * BK];
    __shared__ float Bs[BK * BN];
    int tid = threadIdx.x;
    int tx = tid & 15, ty = tid >> 4;
    float acc[4][4] = {};
    const float* ab = g_ao + (size_t)b * HTOT * SPA;

    for (int k0 = 0; k0 < HTOT; k0 += BK) {
        for (int i = tid; i < BM * BK; i += 256) {
            int row = i / BK, col = i % BK;
            As[i] = w[(size_t)(m0 + row) * HTOT + k0 + col];
        }
        for (int i = tid; i < BK * BN; i += 256) {
            int kk = i / BN, j = i % BN;
            Bs[i] = ab[(size_t)(k0 + kk) * SPA + n0 + j];
        }
        __syncthreads();
        #pragma unroll
        for (int kk = 0; kk < BK; kk++) {
            float a[4], bb[4];
            #pragma unroll
            for (int i = 0; i < 4; i++) a[i] = As[(ty * 4 + i) * BK + kk];
            #pragma unroll
            for (int j = 0; j < 4; j++) bb[j] = Bs[kk * BN + tx * 4 + j];
            #pragma unroll
            for (int i = 0; i < 4; i++)
                #pragma unroll
                for (int j = 0; j < 4; j++) acc[i][j] += a[i] * bb[j];
        }
        __syncthreads();
    }
    #pragma unroll
    for (int i = 0; i < 4; i++) {
        float bv = bias[m0 + ty * 4 + i];
        #pragma unroll
        for (int j = 0; j < 4; j++)
            y[(size_t)(b * C_CH + m0 + ty * 4 + i) * SPA + n0 + tx * 4 + j] =
                acc[i][j] + bv;
    }
}

// ---------------------------------------------------------------------------
extern "C" void kernel_launch(void* const* d_in, const int* in_sizes, int n_in,
                              void* d_out, int out_size) {
    const float* x     = (const float*)d_in[0];
    const float* gamma = (const float*)d_in[1];
    const float* beta  = (const float*)d_in[2];
    const float* w_qkv = (const float*)d_in[3];
    const float* w_out = (const float*)d_in[4];
    const float* b_out = (const float*)d_in[5];
    float* y = (float*)d_out;

    gn_stats<<<BATCH * GROUPS, 256>>>(x);
    qkv_gemm<<<dim3(SPA / BN, QKV_R / BM, BATCH), 256>>>(x, w_qkv, gamma, beta);
    attn_partial<<<dim3(SPA / MT, HEADS * NC, BATCH), 128>>>();
    attn_combine<<<dim3(SPA / 256, HEADS * 4, BATCH), 256>>>();
    out_gemm<<<dim3(SPA / BN, C_CH / BM, BATCH), 256>>>(w_out, b_out, y);
}

// round 17
// speedup vs baseline: 1.8794x; 1.1006x over previous
#include <cuda_runtime.h>
#include <math.h>
#include <cuda_fp16.h>

#define C_CH   128
#define SPA    4096
#define BATCH  2
#define HEADS  4
#define DHEAD  32
#define GROUPS 32
#define CPG    4
#define HTOT   128
#define QKV_R  384
#define EPSV   1e-5f

#define NC     4                 // split-K chunks over keys
#define CHUNK  (SPA / NC)        // 1024 keys per chunk
#define MT     64                // queries per block
#define KT     64                // keys staged per fill (2 x 32 compute halves)

// Scratch (device globals: allocation-free per harness rules)
__device__ float g_qkv [BATCH * QKV_R * SPA];
__device__ float g_ao  [BATCH * HTOT * SPA];
__device__ float g_mean[BATCH * GROUPS];
__device__ float g_rstd[BATCH * GROUPS];
__device__ float g_pacc[BATCH * HEADS * NC * DHEAD * SPA];
__device__ float g_pm  [BATCH * HEADS * NC * SPA];
__device__ float g_pl  [BATCH * HEADS * NC * SPA];

__device__ __forceinline__ float ex2(float x) {
    float r; asm("ex2.approx.ftz.f32 %0, %1;" : "=f"(r) : "f"(x)); return r;
}
// pack two floats into f16x2: first arg -> lower half
__device__ __forceinline__ unsigned pack_h2(float lo, float hi) {
    unsigned r; asm("cvt.rn.f16x2.f32 %0, %1, %2;" : "=r"(r) : "f"(hi), "f"(lo));
    return r;
}
// D += A(16x16,row) * B(16x8,col) ; f16 operands, f32 accum
__device__ __forceinline__ void mma_f16(float* c, const unsigned* a,
                                        unsigned b0, unsigned b1) {
    asm volatile(
        "mma.sync.aligned.m16n8k16.row.col.f32.f16.f16.f32 "
        "{%0,%1,%2,%3}, {%4,%5,%6,%7}, {%8,%9}, {%0,%1,%2,%3};"
        : "+f"(c[0]), "+f"(c[1]), "+f"(c[2]), "+f"(c[3])
        : "r"(a[0]), "r"(a[1]), "r"(a[2]), "r"(a[3]), "r"(b0), "r"(b1));
}

// ---------------------------------------------------------------------------
// 1) GroupNorm statistics
// ---------------------------------------------------------------------------
__global__ __launch_bounds__(256) void gn_stats(const float* __restrict__ x) {
    int bg = blockIdx.x;
    const float* p = x + (size_t)bg * (CPG * SPA);
    float s1 = 0.f, s2 = 0.f;
    for (int i = threadIdx.x; i < CPG * SPA; i += 256) {
        float v = p[i];
        s1 += v; s2 += v * v;
    }
    __shared__ float r1[8], r2[8];
    #pragma unroll
    for (int o = 16; o; o >>= 1) {
        s1 += __shfl_down_sync(0xffffffffu, s1, o);
        s2 += __shfl_down_sync(0xffffffffu, s2, o);
    }
    int w = threadIdx.x >> 5, l = threadIdx.x & 31;
    if (l == 0) { r1[w] = s1; r2[w] = s2; }
    __syncthreads();
    if (w == 0) {
        s1 = (l < 8) ? r1[l] : 0.f;
        s2 = (l < 8) ? r2[l] : 0.f;
        #pragma unroll
        for (int o = 4; o; o >>= 1) {
            s1 += __shfl_down_sync(0xffffffffu, s1, o);
            s2 += __shfl_down_sync(0xffffffffu, s2, o);
        }
        if (l == 0) {
            const float invN = 1.0f / (CPG * SPA);
            float mean = s1 * invN;
            float var  = s2 * invN - mean * mean;
            g_mean[bg] = mean;
            g_rstd[bg] = rsqrtf(var + EPSV);
        }
    }
}

// ---------------------------------------------------------------------------
// 2) QKV GEMM with fused GroupNorm on the activation load
// ---------------------------------------------------------------------------
#define BM 64
#define BN 64
#define BK 32

__global__ __launch_bounds__(256) void qkv_gemm(const float* __restrict__ x,
                                                const float* __restrict__ w,
                                                const float* __restrict__ gamma,
                                                const float* __restrict__ beta) {
    int b  = blockIdx.z;
    int m0 = blockIdx.y * BM;
    int n0 = blockIdx.x * BN;
    __shared__ float As[BM * BK];
    __shared__ float Bs[BK * BN];
    int tid = threadIdx.x;
    int tx = tid & 15, ty = tid >> 4;
    float acc[4][4] = {};
    const float* xb = x + (size_t)b * C_CH * SPA;

    for (int k0 = 0; k0 < C_CH; k0 += BK) {
        for (int i = tid; i < BM * BK; i += 256) {
            int row = i / BK, col = i % BK;
            As[i] = w[(size_t)(m0 + row) * C_CH + k0 + col];
        }
        for (int i = tid; i < BK * BN; i += 256) {
            int kk = i / BN, j = i % BN;
            int c = k0 + kk;
            int g = c >> 2;
            float mv = g_mean[b * GROUPS + g];
            float rs = g_rstd[b * GROUPS + g];
            float v = xb[(size_t)c * SPA + n0 + j];
            Bs[i] = (v - mv) * rs * gamma[c] + beta[c];
        }
        __syncthreads();
        #pragma unroll
        for (int kk = 0; kk < BK; kk++) {
            float a[4], bb[4];
            #pragma unroll
            for (int i = 0; i < 4; i++) a[i] = As[(ty * 4 + i) * BK + kk];
            #pragma unroll
            for (int j = 0; j < 4; j++) bb[j] = Bs[kk * BN + tx * 4 + j];
            #pragma unroll
            for (int i = 0; i < 4; i++)
                #pragma unroll
                for (int j = 0; j < 4; j++) acc[i][j] += a[i] * bb[j];
        }
        __syncthreads();
    }
    float* outb = g_qkv + (size_t)b * QKV_R * SPA;
    #pragma unroll
    for (int i = 0; i < 4; i++)
        #pragma unroll
        for (int j = 0; j < 4; j++)
            outb[(size_t)(m0 + ty * 4 + i) * SPA + n0 + tx * 4 + j] = acc[i][j];
}

// ---------------------------------------------------------------------------
// 3a) Flash attention partial — fp16 mma.sync m16n8k16, register-direct P,
//     single-fp16 QK (8 mmas/half) + fp16 PV (8 mmas/half).
//     KT=64 keys staged per fill, 2x32 compute halves.
//     Grid: (64, HEADS*NC=16, 2) = 2048 blocks of 128 threads.
// ---------------------------------------------------------------------------
__global__ __launch_bounds__(128) void attn_partial() {
    int qt = blockIdx.x;
    int yc = blockIdx.y;
    int b  = blockIdx.z;
    int n  = yc >> 2, c = yc & (NC - 1);
    int t  = threadIdx.x;
    int w  = t >> 5, lane = t & 31;
    int g  = lane >> 2, tg = lane & 3;     // mma fragment coords
    int r0 = w * 16 + g;                   // this thread's first q-row (of 2)

    // smem: Q stage [32][72] f32 (prologue only)
    __shared__ __align__(16) float sQ[2304];
    __shared__ __align__(16) unsigned s_k[KT * 20];    // [key][d-pair] f16x2
    __shared__ __align__(16) unsigned s_v[32 * 36];    // [d][key-pair] f16x2

    const float* qkv_b = g_qkv + (size_t)b * QKV_R * SPA;
    const float* qptr = qkv_b + (size_t)(n * DHEAD) * SPA;
    const float* kptr = qkv_b + (size_t)(HTOT + n * DHEAD) * SPA;
    const float* vptr = qkv_b + (size_t)(2 * HTOT + n * DHEAD) * SPA;
    int s0 = qt * MT;

    const float scale2 = 0.17677669529663687f * 1.4426950408889634f; // /sqrt(32)*log2e

    // ---- stage Q (scaled f32) as [d][72], coalesced + conflict-free ----
    for (int idx = t; idx < MT * DHEAD; idx += 128) {
        int d = idx >> 6, row = idx & 63;
        sQ[d * 72 + row] = qptr[(size_t)d * SPA + s0 + row] * scale2;
    }
    __syncthreads();

    // ---- Q fragments (fp16, packed pairs along d): 2 k16-groups ----
    unsigned qa[2][4];
    #pragma unroll
    for (int ks = 0; ks < 2; ks++) {
        int d = 16 * ks + 2 * tg;
        qa[ks][0] = pack_h2(sQ[d * 72 + r0],       sQ[(d + 1) * 72 + r0]);
        qa[ks][1] = pack_h2(sQ[d * 72 + r0 + 8],   sQ[(d + 1) * 72 + r0 + 8]);
        qa[ks][2] = pack_h2(sQ[(d + 8) * 72 + r0], sQ[(d + 9) * 72 + r0]);
        qa[ks][3] = pack_h2(sQ[(d + 8) * 72 + r0 + 8], sQ[(d + 9) * 72 + r0 + 8]);
    }

    float m0 = -1e30f, m1 = -1e30f, l0 = 0.f, l1 = 0.f;
    float of[4][4] = {};                   // O accum fragments [ntile(d)][4]

    int jbeg = c * CHUNK, jend = jbeg + CHUNK;
    for (int j0 = jbeg; j0 < jend; j0 += KT) {
        __syncthreads();
        // ---- fill K: [key][d2] f16x2 (d pairs), stride 20 ----
        #pragma unroll
        for (int half = 0; half < 2; half++) {
            int j = (t >> 2) + 32 * half;
            #pragma unroll
            for (int k = 0; k < 4; k++) {
                int d2 = (t & 3) + 4 * k;
                int d = 2 * d2;
                s_k[j * 20 + d2] = pack_h2(kptr[(size_t)d * SPA + j0 + j],
                                           kptr[(size_t)(d + 1) * SPA + j0 + j]);
            }
        }
        // ---- fill V: [d][key-pair] f16x2, stride 36 (float2 gmem loads) ----
        {
            int d = t >> 2;
            #pragma unroll
            for (int k = 0; k < 8; k++) {
                int j2 = (t & 3) + 4 * k;
                float2 vv = *(const float2*)&vptr[(size_t)d * SPA + j0 + 2 * j2];
                s_v[d * 36 + j2] = pack_h2(vv.x, vv.y);
            }
        }
        __syncthreads();

        // ---- two 32-key compute halves (no block sync between) ----
        #pragma unroll 1
        for (int half = 0; half < 2; half++) {
            int jb = half * 32;
            // ---- S = Q @ K^T : single fp16 ----
            float sc[4][4] = {};
            #pragma unroll
            for (int ks = 0; ks < 2; ks++) {
                #pragma unroll
                for (int nt = 0; nt < 4; nt++) {
                    int kr = (jb + nt * 8 + g) * 20 + 8 * ks + tg;
                    mma_f16(sc[nt], qa[ks], s_k[kr], s_k[kr + 4]);
                }
            }

            // ---- softmax (log2 domain) on fragments ----
            float rm0 = fmaxf(fmaxf(sc[0][0], sc[0][1]), fmaxf(sc[1][0], sc[1][1]));
            rm0 = fmaxf(rm0, fmaxf(fmaxf(sc[2][0], sc[2][1]), fmaxf(sc[3][0], sc[3][1])));
            float rm1 = fmaxf(fmaxf(sc[0][2], sc[0][3]), fmaxf(sc[1][2], sc[1][3]));
            rm1 = fmaxf(rm1, fmaxf(fmaxf(sc[2][2], sc[2][3]), fmaxf(sc[3][2], sc[3][3])));
            rm0 = fmaxf(rm0, __shfl_xor_sync(0xffffffffu, rm0, 1));
            rm0 = fmaxf(rm0, __shfl_xor_sync(0xffffffffu, rm0, 2));
            rm1 = fmaxf(rm1, __shfl_xor_sync(0xffffffffu, rm1, 1));
            rm1 = fmaxf(rm1, __shfl_xor_sync(0xffffffffu, rm1, 2));
            float nm0 = fmaxf(m0, rm0), nm1 = fmaxf(m1, rm1);
            float c0 = ex2(m0 - nm0), c1 = ex2(m1 - nm1);
            l0 *= c0; l1 *= c1;
            #pragma unroll
            for (int nt = 0; nt < 4; nt++) {
                of[nt][0] *= c0; of[nt][1] *= c0;
                of[nt][2] *= c1; of[nt][3] *= c1;
            }
            m0 = nm0; m1 = nm1;

            // P values per tile nt (rows r0, r0+8; cols 2tg, 2tg+1)
            float p[4][4];
            float ps0 = 0.f, ps1 = 0.f;
            #pragma unroll
            for (int nt = 0; nt < 4; nt++) {
                p[nt][0] = ex2(sc[nt][0] - m0);
                p[nt][1] = ex2(sc[nt][1] - m0);
                p[nt][2] = ex2(sc[nt][2] - m1);
                p[nt][3] = ex2(sc[nt][3] - m1);
                ps0 += p[nt][0] + p[nt][1];
                ps1 += p[nt][2] + p[nt][3];
            }
            l0 += ps0; l1 += ps1;

            // ---- O += P @ V : register-direct A-fragment from p[][] ----
            #pragma unroll
            for (int ks = 0; ks < 2; ks++) {
                unsigned af[4];
                af[0] = pack_h2(p[2 * ks][0],     p[2 * ks][1]);
                af[1] = pack_h2(p[2 * ks][2],     p[2 * ks][3]);
                af[2] = pack_h2(p[2 * ks + 1][0], p[2 * ks + 1][1]);
                af[3] = pack_h2(p[2 * ks + 1][2], p[2 * ks + 1][3]);
                int kp = (jb >> 1) + 8 * ks + tg;   // global key-pair index
                #pragma unroll
                for (int nt = 0; nt < 4; nt++) {
                    unsigned b0 = s_v[(nt * 8 + g) * 36 + kp];
                    unsigned b1 = s_v[(nt * 8 + g) * 36 + kp + 4];
                    mma_f16(of[nt], af, b0, b1);
                }
            }
        }
    }

    // ---- finalize l (quad reduce) and write partials ----
    l0 += __shfl_xor_sync(0xffffffffu, l0, 1);
    l0 += __shfl_xor_sync(0xffffffffu, l0, 2);
    l1 += __shfl_xor_sync(0xffffffffu, l1, 1);
    l1 += __shfl_xor_sync(0xffffffffu, l1, 2);

    size_t base = (size_t)(b * HEADS + n) * NC + c;
    if (tg == 0) {
        g_pm[base * SPA + s0 + r0]     = m0;
        g_pl[base * SPA + s0 + r0]     = l0;
        g_pm[base * SPA + s0 + r0 + 8] = m1;
        g_pl[base * SPA + s0 + r0 + 8] = l1;
    }
    float* pa = g_pacc + base * (DHEAD * SPA);
    #pragma unroll
    for (int nt = 0; nt < 4; nt++) {
        int d0 = nt * 8 + 2 * tg;
        pa[(size_t)d0 * SPA + s0 + r0]           = of[nt][0];
        pa[(size_t)(d0 + 1) * SPA + s0 + r0]     = of[nt][1];
        pa[(size_t)d0 * SPA + s0 + r0 + 8]       = of[nt][2];
        pa[(size_t)(d0 + 1) * SPA + s0 + r0 + 8] = of[nt][3];
    }
}

// ---------------------------------------------------------------------------
// 3b) Combine split-K partials -> g_ao (m/l log2-domain)
// ---------------------------------------------------------------------------
__global__ __launch_bounds__(256) void attn_combine() {
    int t = threadIdx.x;
    int s = blockIdx.x * 256 + t;
    int yb = blockIdx.y;
    int n = yb >> 2, dbase = (yb & 3) * 8;
    int b = blockIdx.z;
    size_t base = (size_t)(b * HEADS + n) * NC;

    float pm[NC];
    float m = -1e30f;
    #pragma unroll
    for (int c = 0; c < NC; c++) {
        pm[c] = g_pm[(base + c) * SPA + s];
        m = fmaxf(m, pm[c]);
    }
    float wgt[NC];
    float L = 0.f;
    #pragma unroll
    for (int c = 0; c < NC; c++) {
        wgt[c] = ex2(fmaxf(pm[c] - m, -120.0f));
        L += g_pl[(base + c) * SPA + s] * wgt[c];
    }
    float invL = 1.0f / L;
    #pragma unroll
    for (int c = 0; c < NC; c++) wgt[c] *= invL;

    float* ao = g_ao + ((size_t)b * HTOT + n * DHEAD) * SPA;
    #pragma unroll
    for (int dd = 0; dd < 8; dd++) {
        int d = dbase + dd;
        float a = 0.f;
        #pragma unroll
        for (int c = 0; c < NC; c++)
            a += g_pacc[((base + c) * DHEAD + d) * SPA + s] * wgt[c];
        ao[(size_t)d * SPA + s] = a;
    }
}

// ---------------------------------------------------------------------------
// 4) Output projection
// ---------------------------------------------------------------------------
__global__ __launch_bounds__(256) void out_gemm(const float* __restrict__ w,
                                                const float* __restrict__ bias,
                                                float* __restrict__ y) {
    int b  = blockIdx.z;
    int m0 = blockIdx.y * BM;
    int n0 = blockIdx.x * BN;
    __shared__ float As[BM * BK];
    __shared__ float Bs[BK * BN];
    int tid = threadIdx.x;
    int tx = tid & 15, ty = tid >> 4;
    float acc[4][4] = {};
    const float* ab = g_ao + (size_t)b * HTOT * SPA;

    for (int k0 = 0; k0 < HTOT; k0 += BK) {
        for (int i = tid; i < BM * BK; i += 256) {
            int row = i / BK, col = i % BK;
            As[i] = w[(size_t)(m0 + row) * HTOT + k0 + col];
        }
        for (int i = tid; i < BK * BN; i += 256) {
            int kk = i / BN, j = i % BN;
            Bs[i] = ab[(size_t)(k0 + kk) * SPA + n0 + j];
        }
        __syncthreads();
        #pragma unroll
        for (int kk = 0; kk < BK; kk++) {
            float a[4], bb[4];
            #pragma unroll
            for (int i = 0; i < 4; i++) a[i] = As[(ty * 4 + i) * BK + kk];
            #pragma unroll
            for (int j = 0; j < 4; j++) bb[j] = Bs[kk * BN + tx * 4 + j];
            #pragma unroll
            for (int i = 0; i < 4; i++)
                #pragma unroll
                for (int j = 0; j < 4; j++) acc[i][j] += a[i] * bb[j];
        }
        __syncthreads();
    }
    #pragma unroll
    for (int i = 0; i < 4; i++) {
        float bv = bias[m0 + ty * 4 + i];
        #pragma unroll
        for (int j = 0; j < 4; j++)
            y[(size_t)(b * C_CH + m0 + ty * 4 + i) * SPA + n0 + tx * 4 + j] =
                acc[i][j] + bv;
    }
}

// ---------------------------------------------------------------------------
extern "C" void kernel_launch(void* const* d_in, const int* in_sizes, int n_in,
                              void* d_out, int out_size) {
    const float* x     = (const float*)d_in[0];
    const float* gamma = (const float*)d_in[1];
    const float* beta  = (const float*)d_in[2];
    const float* w_qkv = (const float*)d_in[3];
    const float* w_out = (const float*)d_in[4];
    const float* b_out = (const float*)d_in[5];
    float* y = (float*)d_out;

    gn_stats<<<BATCH * GROUPS, 256>>>(x);
    qkv_gemm<<<dim3(SPA / BN, QKV_R / BM, BATCH), 256>>>(x, w_qkv, gamma, beta);
    attn_partial<<<dim3(SPA / MT, HEADS * NC, BATCH), 128>>>();
    attn_combine<<<dim3(SPA / 256, HEADS * 4, BATCH), 256>>>();
    out_gemm<<<dim3(SPA / BN, C_CH / BM, BATCH), 256>>>(w_out, b_out, y);
}